// round 7
// baseline (speedup 1.0000x reference)
#include <cuda_runtime.h>
#include <cuda_fp16.h>
#include <cstdint>
#include <math.h>

// ---------------- problem constants ----------------
#define NSYM   200001
#define PADID  200000
#define BQ     1024
#define FEW    5
#define NB     200
#define DM     256
#define DI     512
#define HID    512
#define G4     2048
#define NROWS  (BQ + FEW)

typedef __half fp16;

// ---------------- device scratch ----------------
__device__ float g_proj[(size_t)NSYM * 256];
__device__ fp16  g_embhi[(size_t)NSYM * 128];
__device__ fp16  g_Wphi[256 * 128], g_Wplo[256 * 128];
__device__ fp16  g_p1hi[512 * 256], g_p1lo[512 * 256];
__device__ fp16  g_p2hi[256 * 512], g_p2lo[256 * 512];
__device__ fp16  g_Wihhi[2048 * 256], g_Wihlo[2048 * 256];
__device__ fp16  g_Whhhi[2048 * 256], g_Whhlo[2048 * 256];
__device__ float g_biasproj[256];
__device__ float g_bsum[G4];
__device__ float g_xcat[NROWS * DM];
__device__ fp16  g_xcathi[NROWS * DM];
__device__ fp16  g_henchi[NROWS * DI];
__device__ float g_oenc[NROWS * DM];
__device__ float g_enc[NROWS * DM];
__device__ fp16  g_enchi[NROWS * DM];
__device__ float g_support[DM];
__device__ float g_sconst[G4];
__device__ float g_qWihb[BQ * G4];
__device__ float g_gates[BQ * G4];
__device__ float g_h[BQ * DM];
__device__ fp16  g_hhi[BQ * DM];
__device__ float g_c[BQ * HID];
__device__ int   g_is64;

// ---------------- helpers ----------------
__device__ __forceinline__ uint32_t smem_u32(const void* p) {
    uint32_t a;
    asm("{ .reg .u64 t; cvta.to.shared.u64 t, %1; cvt.u32.u64 %0, t; }" : "=r"(a) : "l"(p));
    return a;
}
__device__ __forceinline__ void ldmatrix4(uint32_t addr, uint32_t& r0, uint32_t& r1,
                                          uint32_t& r2, uint32_t& r3) {
    asm volatile("ldmatrix.sync.aligned.m8n8.x4.shared.b16 {%0,%1,%2,%3}, [%4];"
                 : "=r"(r0), "=r"(r1), "=r"(r2), "=r"(r3) : "r"(addr));
}
__device__ __forceinline__ void mma16816(float* d, const uint32_t* a,
                                         uint32_t b0, uint32_t b1) {
    asm volatile(
        "mma.sync.aligned.m16n8k16.row.col.f32.f16.f16.f32 "
        "{%0,%1,%2,%3}, {%4,%5,%6,%7}, {%8,%9}, {%0,%1,%2,%3};"
        : "+f"(d[0]), "+f"(d[1]), "+f"(d[2]), "+f"(d[3])
        : "r"(a[0]), "r"(a[1]), "r"(a[2]), "r"(a[3]), "r"(b0), "r"(b1));
}
__device__ __forceinline__ uint32_t pack_h2(fp16 a, fp16 b) {
    __half2 t(a, b);
    return *reinterpret_cast<uint32_t*>(&t);
}
__device__ __forceinline__ void split1(float v, fp16& h, fp16& l) {
    h = __float2half(v);
    l = __float2half(v - __half2float(h));
}
// pack 8 floats into fp16 hi (and optionally lo) uint4s
__device__ __forceinline__ uint4 cvt8(const float* f) {
    return make_uint4(pack_h2(__float2half(f[0]), __float2half(f[1])),
                      pack_h2(__float2half(f[2]), __float2half(f[3])),
                      pack_h2(__float2half(f[4]), __float2half(f[5])),
                      pack_h2(__float2half(f[6]), __float2half(f[7])));
}
__device__ __forceinline__ void split8(const float* f, uint4& hi, uint4& lo) {
    fp16 h[8], l[8];
#pragma unroll
    for (int i = 0; i < 8; ++i) split1(f[i], h[i], l[i]);
    hi = make_uint4(pack_h2(h[0], h[1]), pack_h2(h[2], h[3]),
                    pack_h2(h[4], h[5]), pack_h2(h[6], h[7]));
    lo = make_uint4(pack_h2(l[0], l[1]), pack_h2(l[2], l[3]),
                    pack_h2(l[4], l[5]), pack_h2(l[6], l[7]));
}

// ---------------- prep: detect dtype, Wproj reshuffle+split, biases --------
__global__ void prep_kernel(const float* __restrict__ gcnW,
                            const float* __restrict__ wb,
                            const float* __restrict__ gb,
                            const float* __restrict__ bih,
                            const float* __restrict__ bhh,
                            const int* __restrict__ qlc_i32) {
    int idx = blockIdx.x * blockDim.x + threadIdx.x;
    if (idx == 0) {
        int any = 0;
        for (int i = 1; i < 2 * NB; i += 2) any |= qlc_i32[i];
        g_is64 = (any == 0) ? 1 : 0;
    }
    if (idx < 256 * 128) {
        int j = idx >> 7, e = idx & 127;
        float v = (j < 128) ? gcnW[j * 256 + e] : gcnW[(j - 128) * 256 + 128 + e];
        fp16 h, l;
        split1(v, h, l);
        g_Wphi[idx] = h;
        g_Wplo[idx] = l;
    }
    if (idx < 256) g_biasproj[idx] = (idx < 128) ? (wb[idx] + gb[idx]) : 0.f;
    if (idx < G4)  g_bsum[idx] = bih[idx] + bhh[idx];
}

// ---------------- emb -> fp16 hi only (vectorized x8) ----------------
__global__ void cvt_emb_kernel(const float* __restrict__ emb, int total8) {
    int i = blockIdx.x * blockDim.x + threadIdx.x;
    if (i >= total8) return;
    int e0 = i * 8;
    float4 v0 = *reinterpret_cast<const float4*>(emb + e0);
    float4 v1 = *reinterpret_cast<const float4*>(emb + e0 + 4);
    float f[8] = {v0.x, v0.y, v0.z, v0.w, v1.x, v1.y, v1.z, v1.w};
    *reinterpret_cast<uint4*>(g_embhi + e0) = cvt8(f);
}

// ---------------- split all 4 B-weights into fp16 hi/lo (one kernel) -------
#define T8_P1 (512 * 256 / 8)
#define T8_P2 (256 * 512 / 8)
#define T8_WI (2048 * 256 / 8)
#define T8_WH (2048 * 256 / 8)
__global__ void split_all_kernel(const float* __restrict__ p1W,
                                 const float* __restrict__ p2W,
                                 const float* __restrict__ Wih,
                                 const float* __restrict__ Whh) {
    int i = blockIdx.x * blockDim.x + threadIdx.x;
    const float* src;
    fp16 *hi, *lo;
    int e0;
    if (i < T8_P1) {
        e0 = i * 8; src = p1W + e0; hi = g_p1hi + e0; lo = g_p1lo + e0;
    } else if (i < T8_P1 + T8_P2) {
        e0 = (i - T8_P1) * 8; src = p2W + e0; hi = g_p2hi + e0; lo = g_p2lo + e0;
    } else if (i < T8_P1 + T8_P2 + T8_WI) {
        e0 = (i - T8_P1 - T8_P2) * 8; src = Wih + e0; hi = g_Wihhi + e0; lo = g_Wihlo + e0;
    } else if (i < T8_P1 + T8_P2 + T8_WI + T8_WH) {
        e0 = (i - T8_P1 - T8_P2 - T8_WI) * 8;
        int row = e0 >> 8, col = e0 & 255;          // Whh: take cols 0..255 of ldw=512
        src = Whh + (size_t)row * 512 + col;
        hi = g_Whhhi + e0; lo = g_Whhlo + e0;
    } else return;
    float4 v0 = *reinterpret_cast<const float4*>(src);
    float4 v1 = *reinterpret_cast<const float4*>(src + 4);
    float f[8] = {v0.x, v0.y, v0.z, v0.w, v1.x, v1.y, v1.z, v1.w};
    uint4 h, l;
    split8(f, h, l);
    *reinterpret_cast<uint4*>(hi) = h;
    *reinterpret_cast<uint4*>(lo) = l;
}

// =====================================================================
// proj_mma: g_proj[NSYM,256] = emb @ Wproj^T (+bias)
// A = emb fp16 (single), B = Wproj fp16 hi+lo. 2-pass accumulation.
// CTA tile 128x256, 512 threads, warps 4Mx4N of 32x64.
// =====================================================================
#define ROWB 272
#define PA_OFF 0
#define PBH_OFF (128 * ROWB)                 // 34816
#define PBL_OFF (PBH_OFF + 256 * ROWB)       // 104448
#define PROJ_SMEM (PBL_OFF + 256 * ROWB)     // 174080

__global__ void __launch_bounds__(512, 1)
proj_mma_kernel() {
    extern __shared__ char sm[];
    const uint32_t sbase = smem_u32(sm);
    const int tid = threadIdx.x;
    const int mbase = blockIdx.x * 128;

    // A tile: 128 rows x 128 fp16
#pragma unroll
    for (int i = 0; i < 4; ++i) {
        int c = tid + i * 512;
        if (c >= 2048) break;
        int row = c >> 4, ch = c & 15;
        int grow = mbase + row;
        uint4 h = make_uint4(0, 0, 0, 0);
        if (grow < NSYM)
            h = *reinterpret_cast<const uint4*>(g_embhi + (size_t)grow * 128 + ch * 8);
        *reinterpret_cast<uint4*>(sm + PA_OFF + row * ROWB + ch * 16) = h;
    }
    // B tiles: 256 rows x 128 fp16 (hi & lo)
#pragma unroll
    for (int i = 0; i < 8; ++i) {
        int c = tid + i * 512;
        int row = c >> 4, ch = c & 15;
        uint4 h = *reinterpret_cast<const uint4*>(g_Wphi + row * 128 + ch * 8);
        uint4 l = *reinterpret_cast<const uint4*>(g_Wplo + row * 128 + ch * 8);
        int off = row * ROWB + ch * 16;
        *reinterpret_cast<uint4*>(sm + PBH_OFF + off) = h;
        *reinterpret_cast<uint4*>(sm + PBL_OFF + off) = l;
    }
    __syncthreads();

    const int warp = tid >> 5, lane = tid & 31;
    const int wm = warp & 3, wn = warp >> 2;
    const int m0 = wm * 32, n0 = wn * 64;

    float acc[2][8][4];
#pragma unroll
    for (int i = 0; i < 2; ++i)
#pragma unroll
        for (int j = 0; j < 8; ++j)
#pragma unroll
            for (int q = 0; q < 4; ++q) acc[i][j][q] = 0.f;

    const int a_row = (lane & 15);
    const int a_kadd = (lane >> 4) << 3;
    const int b_row = ((lane >> 4) << 3) + (lane & 7);
    const int b_kadd = ((lane >> 3) & 1) << 3;

#pragma unroll
    for (int ks = 0; ks < 8; ++ks) {
        const int k0 = ks * 16;
        uint32_t ra[2][4];
#pragma unroll
        for (int mi = 0; mi < 2; ++mi)
            ldmatrix4(sbase + PA_OFF + (m0 + mi * 16 + a_row) * ROWB + (k0 + a_kadd) * 2,
                      ra[mi][0], ra[mi][1], ra[mi][2], ra[mi][3]);
        uint32_t rbh[4][4], rbl[4][4];
#pragma unroll
        for (int np = 0; np < 4; ++np) {
            uint32_t boff = (n0 + np * 16 + b_row) * ROWB + (k0 + b_kadd) * 2;
            ldmatrix4(sbase + PBH_OFF + boff, rbh[np][0], rbh[np][1], rbh[np][2], rbh[np][3]);
            ldmatrix4(sbase + PBL_OFF + boff, rbl[np][0], rbl[np][1], rbl[np][2], rbl[np][3]);
        }
#pragma unroll
        for (int mi = 0; mi < 2; ++mi)
#pragma unroll
            for (int ni = 0; ni < 8; ++ni) {
                mma16816(acc[mi][ni], ra[mi],
                         rbh[ni >> 1][(ni & 1) * 2 + 0], rbh[ni >> 1][(ni & 1) * 2 + 1]);
                mma16816(acc[mi][ni], ra[mi],
                         rbl[ni >> 1][(ni & 1) * 2 + 0], rbl[ni >> 1][(ni & 1) * 2 + 1]);
            }
    }

    const int rbase = mbase + m0;
#pragma unroll
    for (int mi = 0; mi < 2; ++mi) {
#pragma unroll
        for (int ni = 0; ni < 8; ++ni) {
            int col = n0 + ni * 8 + (lane & 3) * 2;
            float b0 = g_biasproj[col], b1 = g_biasproj[col + 1];
            int r0 = rbase + mi * 16 + (lane >> 2);
            int r1 = r0 + 8;
            if (r0 < NSYM)
                *reinterpret_cast<float2*>(g_proj + (size_t)r0 * 256 + col) =
                    make_float2(acc[mi][ni][0] + b0, acc[mi][ni][1] + b1);
            if (r1 < NSYM)
                *reinterpret_cast<float2*>(g_proj + (size_t)r1 * 256 + col) =
                    make_float2(acc[mi][ni][2] + b0, acc[mi][ni][3] + b1);
        }
    }
}

// =====================================================================
// generic 2-pass HMMA GEMM: C[M,N] = A[M,K](fp16) @ (Bhi+Blo)[N,K]^T
// CTA tile 128x128, K-chunk 64, 256 threads (warps 4Mx2N of 32x64).
// =====================================================================
#define KROWB 144
#define HG_A  0
#define HG_BH (128 * KROWB)
#define HG_BL (2 * 128 * KROWB)
#define HG_SMEM (3 * 128 * KROWB)   // 55296

__global__ void __launch_bounds__(256, 2)
hgemm2(int M, int N, int K,
       const fp16* __restrict__ A,
       const fp16* __restrict__ Bhi, const fp16* __restrict__ Blo,
       const float* __restrict__ bias, const float* __restrict__ addMat,
       float* __restrict__ C, fp16* __restrict__ Chi, int doRelu) {
    extern __shared__ char sm[];
    const uint32_t sbase = smem_u32(sm);
    const int tid = threadIdx.x;
    const int mtile = blockIdx.y * 128, ntile = blockIdx.x * 128;

    const int warp = tid >> 5, lane = tid & 31;
    const int wm = warp & 3, wn = warp >> 2;
    const int m0 = wm * 32, n0 = wn * 64;

    float acc[2][8][4];
#pragma unroll
    for (int i = 0; i < 2; ++i)
#pragma unroll
        for (int j = 0; j < 8; ++j)
#pragma unroll
            for (int q = 0; q < 4; ++q) acc[i][j][q] = 0.f;

    const int a_row = (lane & 15);
    const int a_kadd = (lane >> 4) << 3;
    const int b_row = ((lane >> 4) << 3) + (lane & 7);
    const int b_kadd = ((lane >> 3) & 1) << 3;

    for (int kc = 0; kc < K; kc += 64) {
#pragma unroll
        for (int i = 0; i < 2; ++i) {     // A: 128 rows x 64 fp16 = 512 chunks
            int c = tid + i * 256;
            int row = c >> 2, ch = c & 3;
            int gk = kc + ch * 16;        // 16 fp16 = 32B? no: chunk = 8 fp16 = 16B
            // (re-derive: 128 rows x 64 fp16 = 8192 fp16 = 1024 x 8fp16 chunks)
            (void)row; (void)ch; (void)gk;
        }
        // A: 1024 chunks of 8 fp16
#pragma unroll
        for (int i = 0; i < 4; ++i) {
            int c = tid + i * 256;
            if (c >= 1024) break;
            int row = c >> 3, ch = c & 7;
            int gk = kc + ch * 8;
            int grow = mtile + row;
            uint4 h = make_uint4(0, 0, 0, 0);
            if (grow < M)
                h = *reinterpret_cast<const uint4*>(A + (size_t)grow * K + gk);
            *reinterpret_cast<uint4*>(sm + HG_A + row * KROWB + ch * 16) = h;
        }
        // B hi/lo: 1024 chunks each
#pragma unroll
        for (int i = 0; i < 4; ++i) {
            int c = tid + i * 256;
            int row = c >> 3, ch = c & 7;
            int gk = kc + ch * 8;
            int grow = ntile + row;
            uint4 h = *reinterpret_cast<const uint4*>(Bhi + (size_t)grow * K + gk);
            uint4 l = *reinterpret_cast<const uint4*>(Blo + (size_t)grow * K + gk);
            int off = row * KROWB + ch * 16;
            *reinterpret_cast<uint4*>(sm + HG_BH + off) = h;
            *reinterpret_cast<uint4*>(sm + HG_BL + off) = l;
        }
        __syncthreads();

#pragma unroll
        for (int ks = 0; ks < 4; ++ks) {
            const int k0 = ks * 16;
            uint32_t ra[2][4];
#pragma unroll
            for (int mi = 0; mi < 2; ++mi)
                ldmatrix4(sbase + HG_A + (m0 + mi * 16 + a_row) * KROWB + (k0 + a_kadd) * 2,
                          ra[mi][0], ra[mi][1], ra[mi][2], ra[mi][3]);
            uint32_t rbh[4][4], rbl[4][4];
#pragma unroll
            for (int np = 0; np < 4; ++np) {
                uint32_t boff = (n0 + np * 16 + b_row) * KROWB + (k0 + b_kadd) * 2;
                ldmatrix4(sbase + HG_BH + boff, rbh[np][0], rbh[np][1], rbh[np][2], rbh[np][3]);
                ldmatrix4(sbase + HG_BL + boff, rbl[np][0], rbl[np][1], rbl[np][2], rbl[np][3]);
            }
#pragma unroll
            for (int mi = 0; mi < 2; ++mi)
#pragma unroll
                for (int ni = 0; ni < 8; ++ni) {
                    mma16816(acc[mi][ni], ra[mi],
                             rbh[ni >> 1][(ni & 1) * 2 + 0], rbh[ni >> 1][(ni & 1) * 2 + 1]);
                    mma16816(acc[mi][ni], ra[mi],
                             rbl[ni >> 1][(ni & 1) * 2 + 0], rbl[ni >> 1][(ni & 1) * 2 + 1]);
                }
        }
        __syncthreads();
    }

#pragma unroll
    for (int mi = 0; mi < 2; ++mi) {
#pragma unroll
        for (int ni = 0; ni < 8; ++ni) {
            int col = ntile + n0 + ni * 8 + (lane & 3) * 2;
            float b0 = bias ? bias[col] : 0.f;
            float b1 = bias ? bias[col + 1] : 0.f;
#pragma unroll
            for (int half = 0; half < 2; ++half) {
                int r = mtile + m0 + mi * 16 + (lane >> 2) + half * 8;
                if (r >= M) continue;
                float vx = acc[mi][ni][half * 2 + 0] + b0;
                float vy = acc[mi][ni][half * 2 + 1] + b1;
                if (addMat) {
                    vx += addMat[(size_t)r * N + col];
                    vy += addMat[(size_t)r * N + col + 1];
                }
                if (doRelu) { vx = fmaxf(vx, 0.f); vy = fmaxf(vy, 0.f); }
                if (C)
                    *reinterpret_cast<float2*>(C + (size_t)r * N + col) = make_float2(vx, vy);
                if (Chi)
                    *reinterpret_cast<uint32_t*>(Chi + (size_t)r * N + col) =
                        pack_h2(__float2half(vx), __float2half(vy));
            }
        }
    }
}

// ---------------- neighbor encoder ----------------
__global__ void __launch_bounds__(128)
neighbor_kernel(const void* qlc, const void* qrc, const void* slc, const void* src) {
    __shared__ int sidx[2 * NB];
    int b = blockIdx.x;
    const void* conn;
    int node, off;
    if (b < BQ)                { conn = qlc; node = b;                off = node * DM; }
    else if (b < 2 * BQ)       { conn = qrc; node = b - BQ;           off = node * DM + 128; }
    else if (b < 2 * BQ + FEW) { conn = slc; node = b - 2 * BQ;       off = (BQ + node) * DM; }
    else                       { conn = src; node = b - 2 * BQ - FEW; off = (BQ + node) * DM + 128; }

    int tid = threadIdx.x;
    size_t base = (size_t)node * (2 * NB);
    if (g_is64) {
        const long long* p = (const long long*)conn;
        for (int t = tid; t < 2 * NB; t += 128) sidx[t] = (int)p[base + t];
    } else {
        const int* p = (const int*)conn;
        for (int t = tid; t < 2 * NB; t += 128) sidx[t] = p[base + t];
    }
    __syncthreads();

    const float* __restrict__ proj = g_proj;
    float m = -INFINITY;
#pragma unroll 2
    for (int k = 0; k < NB; ++k) {
        int rel = sidx[2 * k], ent = sidx[2 * k + 1];
        if (rel == PADID || ent == PADID) continue;
        float v = proj[rel * 256 + tid] + proj[ent * 256 + 128 + tid];
        v = (v > 0.f) ? v : 0.1f * v;
        m = fmaxf(m, v);
    }
    float t = tanhf(m);
    g_xcat[off + tid] = t;
    g_xcathi[off + tid] = __float2half(t);
}

// ---------------- layernorm ----------------
__global__ void ln_kernel(const float* __restrict__ lg, const float* __restrict__ lb) {
    __shared__ float red[256];
    int row = blockIdx.x, t = threadIdx.x;
    float v = g_oenc[row * DM + t];
    red[t] = v;
    __syncthreads();
    for (int s = 128; s > 0; s >>= 1) { if (t < s) red[t] += red[t + s]; __syncthreads(); }
    float mu = red[0] * (1.f / 256.f);
    __syncthreads();
    float d = v - mu;
    red[t] = d * d;
    __syncthreads();
    for (int s = 128; s > 0; s >>= 1) { if (t < s) red[t] += red[t + s]; __syncthreads(); }
    float var = red[0] * (1.f / 256.f);
    float o = d * rsqrtf(var + 1e-5f) * lg[t] + lb[t];
    g_enc[row * DM + t] = o;
    g_enchi[row * DM + t] = __float2half(o);
}

// ---------------- mean + sconst fused (1 block, 1024 threads) ----------------
__global__ void meansconst_kernel(const float* __restrict__ Whh) {
    __shared__ float sup[256];
    int t = threadIdx.x;
    if (t < 256) {
        float s = 0.f;
        for (int r = 0; r < FEW; ++r) s += g_enc[(BQ + r) * DM + t];
        s *= (1.f / FEW);
        sup[t] = s;
        g_support[t] = s;
    }
    __syncthreads();
#pragma unroll
    for (int g = t; g < G4; g += 1024) {
        float s = 0.f;
        const float* w = Whh + (size_t)g * 512 + 256;
#pragma unroll 4
        for (int i = 0; i < DM; ++i) s += sup[i] * w[i];
        g_sconst[g] = s;
    }
}

// ---------------- LSTM elementwise step ----------------
__device__ __forceinline__ float sigm(float x) { return 1.f / (1.f + expf(-x)); }

__global__ void lstm_kernel(const float* __restrict__ G, int firstStep) {
    int idx = blockIdx.x * blockDim.x + threadIdx.x;
    if (idx >= BQ * HID) return;
    int n = idx >> 9, j = idx & 511;
    const float* g = G + (size_t)n * G4;
    float gi = g[j], gf = g[512 + j], gg = g[1024 + j], go = g[1536 + j];
    float c  = firstStep ? 0.f : g_c[idx];
    float cn = sigm(gf) * c + sigm(gi) * tanhf(gg);
    g_c[idx] = cn;
    if (j < DM) {
        float hv = g_enc[n * DM + j] + sigm(go) * tanhf(cn);
        g_h[n * DM + j] = hv;
        g_hhi[n * DM + j] = __float2half(hv);
    }
}

// ---------------- final dot ----------------
__global__ void final_kernel(float* __restrict__ out) {
    int n = (blockIdx.x * blockDim.x + threadIdx.x) >> 5;
    int lane = threadIdx.x & 31;
    if (n >= BQ) return;
    float s = 0.f;
    for (int i = lane; i < DM; i += 32)
        s += g_h[n * DM + i] * g_support[i];
#pragma unroll
    for (int o = 16; o > 0; o >>= 1) s += __shfl_down_sync(0xffffffffu, s, o);
    if (lane == 0) out[n] = s;
}

// ---------------- launch ----------------
extern "C" void kernel_launch(void* const* d_in, const int* in_sizes, int n_in,
                              void* d_out, int out_size) {
    const void* qlc = d_in[0];
    const void* qrc = d_in[1];
    const void* slc = d_in[2];
    const void* src = d_in[3];
    const float* emb  = (const float*)d_in[8];
    const float* gcnW = (const float*)d_in[9];
    const float* wb   = (const float*)d_in[10];
    const float* gb   = (const float*)d_in[11];
    const float* p1W  = (const float*)d_in[12];
    const float* p1b  = (const float*)d_in[13];
    const float* p2W  = (const float*)d_in[14];
    const float* p2b  = (const float*)d_in[15];
    const float* lng  = (const float*)d_in[16];
    const float* lnb  = (const float*)d_in[17];
    const float* Wih  = (const float*)d_in[18];
    const float* Whh  = (const float*)d_in[19];
    const float* bih  = (const float*)d_in[20];
    const float* bhh  = (const float*)d_in[21];

    fp16 *p1hi, *p1lo, *p2hi, *p2lo, *Wihhi, *Wihlo, *Whhhi, *Whhlo;
    fp16 *xcathi, *henchi, *enchi, *hhi;
    float *xcat, *oenc, *sconst, *qWihb, *gates, *bsum;
    cudaGetSymbolAddress((void**)&p1hi,  g_p1hi);
    cudaGetSymbolAddress((void**)&p1lo,  g_p1lo);
    cudaGetSymbolAddress((void**)&p2hi,  g_p2hi);
    cudaGetSymbolAddress((void**)&p2lo,  g_p2lo);
    cudaGetSymbolAddress((void**)&Wihhi, g_Wihhi);
    cudaGetSymbolAddress((void**)&Wihlo, g_Wihlo);
    cudaGetSymbolAddress((void**)&Whhhi, g_Whhhi);
    cudaGetSymbolAddress((void**)&Whhlo, g_Whhlo);
    cudaGetSymbolAddress((void**)&xcathi, g_xcathi);
    cudaGetSymbolAddress((void**)&henchi, g_henchi);
    cudaGetSymbolAddress((void**)&enchi,  g_enchi);
    cudaGetSymbolAddress((void**)&hhi,    g_hhi);
    cudaGetSymbolAddress((void**)&xcat,   g_xcat);
    cudaGetSymbolAddress((void**)&oenc,   g_oenc);
    cudaGetSymbolAddress((void**)&sconst, g_sconst);
    cudaGetSymbolAddress((void**)&qWihb,  g_qWihb);
    cudaGetSymbolAddress((void**)&gates,  g_gates);
    cudaGetSymbolAddress((void**)&bsum,   g_bsum);

    prep_kernel<<<128, 256>>>(gcnW, wb, gb, bih, bhh, (const int*)qlc);
    cvt_emb_kernel<<<(NSYM * 16 + 255) / 256, 256>>>(emb, NSYM * 16);
    split_all_kernel<<<(T8_P1 + T8_P2 + T8_WI + T8_WH + 255) / 256, 256>>>(p1W, p2W, Wih, Whh);

    cudaFuncSetAttribute(proj_mma_kernel,
                         cudaFuncAttributeMaxDynamicSharedMemorySize, PROJ_SMEM);
    proj_mma_kernel<<<(NSYM + 127) / 128, 512, PROJ_SMEM>>>();

    neighbor_kernel<<<2 * BQ + 2 * FEW, 128>>>(qlc, qrc, slc, src);

    cudaFuncSetAttribute(hgemm2,
                         cudaFuncAttributeMaxDynamicSharedMemorySize, HG_SMEM);

    // henc = relu(xcat@p1W^T + p1b) -> fp16 only
    hgemm2<<<dim3(512 / 128, (NROWS + 127) / 128), 256, HG_SMEM>>>(
        NROWS, 512, 256, xcathi, p1hi, p1lo, p1b, nullptr, nullptr, henchi, 1);
    // oenc = henc@p2W^T + p2b + xcat
    hgemm2<<<dim3(256 / 128, (NROWS + 127) / 128), 256, HG_SMEM>>>(
        NROWS, 256, 512, henchi, p2hi, p2lo, p2b, xcat, oenc, nullptr, 0);
    ln_kernel<<<NROWS, 256>>>(lng, lnb);

    meansconst_kernel<<<1, 1024>>>(Whh);

    // qWihb = enc@Wih^T + (b_ih + b_hh)
    hgemm2<<<dim3(G4 / 128, BQ / 128), 256, HG_SMEM>>>(
        BQ, G4, 256, enchi, Wihhi, Wihlo, bsum, nullptr, qWihb, nullptr, 0);

    lstm_kernel<<<(BQ * HID + 255) / 256, 256>>>(qWihb, 1);

    for (int s = 1; s < 4; ++s) {
        hgemm2<<<dim3(G4 / 128, BQ / 128), 256, HG_SMEM>>>(
            BQ, G4, 256, hhi, Whhhi, Whhlo, sconst, qWihb, gates, nullptr, 0);
        lstm_kernel<<<(BQ * HID + 255) / 256, 256>>>(gates, 0);
    }

    final_kernel<<<(BQ * 32 + 255) / 256, 256>>>((float*)d_out);
}

// round 8
// speedup vs baseline: 1.7852x; 1.7852x over previous
#include <cuda_runtime.h>
#include <cuda_fp16.h>
#include <cstdint>
#include <math.h>

// ---------------- problem constants ----------------
#define NSYM   200001
#define PADID  200000
#define BQ     1024
#define FEW    5
#define NB     200
#define DM     256
#define DI     512
#define HID    512
#define G4     2048
#define NROWS  (BQ + FEW)

typedef __half fp16;

// ---------------- device scratch ----------------
__device__ fp16  g_projh[(size_t)NSYM * 256];  // fp16 projected table
__device__ fp16  g_embhi[(size_t)NSYM * 128];
__device__ fp16  g_Wphi[256 * 128], g_Wplo[256 * 128];
__device__ fp16  g_p1hi[512 * 256], g_p1lo[512 * 256];
__device__ fp16  g_p2hi[256 * 512], g_p2lo[256 * 512];
__device__ fp16  g_Wihhi[2048 * 256], g_Wihlo[2048 * 256];
__device__ fp16  g_Whhhi[2048 * 256], g_Whhlo[2048 * 256];
__device__ float g_biasproj[256];
__device__ float g_bsum[G4];
__device__ float g_xcat[NROWS * DM];
__device__ fp16  g_xcathi[NROWS * DM];
__device__ fp16  g_henchi[NROWS * DI];
__device__ float g_oenc[NROWS * DM];
__device__ float g_enc[NROWS * DM];
__device__ fp16  g_enchi[NROWS * DM];
__device__ float g_support[DM];
__device__ float g_sconst[G4];
__device__ float g_qWihb[BQ * G4];
__device__ float g_gates[BQ * G4];
__device__ float g_h[BQ * DM];
__device__ fp16  g_hhi[BQ * DM];
__device__ float g_c[BQ * HID];
__device__ int   g_is64;

// ---------------- helpers ----------------
__device__ __forceinline__ uint32_t smem_u32(const void* p) {
    uint32_t a;
    asm("{ .reg .u64 t; cvta.to.shared.u64 t, %1; cvt.u32.u64 %0, t; }" : "=r"(a) : "l"(p));
    return a;
}
__device__ __forceinline__ void ldmatrix4(uint32_t addr, uint32_t& r0, uint32_t& r1,
                                          uint32_t& r2, uint32_t& r3) {
    asm volatile("ldmatrix.sync.aligned.m8n8.x4.shared.b16 {%0,%1,%2,%3}, [%4];"
                 : "=r"(r0), "=r"(r1), "=r"(r2), "=r"(r3) : "r"(addr));
}
__device__ __forceinline__ void mma16816(float* d, const uint32_t* a,
                                         uint32_t b0, uint32_t b1) {
    asm volatile(
        "mma.sync.aligned.m16n8k16.row.col.f32.f16.f16.f32 "
        "{%0,%1,%2,%3}, {%4,%5,%6,%7}, {%8,%9}, {%0,%1,%2,%3};"
        : "+f"(d[0]), "+f"(d[1]), "+f"(d[2]), "+f"(d[3])
        : "r"(a[0]), "r"(a[1]), "r"(a[2]), "r"(a[3]), "r"(b0), "r"(b1));
}
__device__ __forceinline__ uint32_t pack_h2(fp16 a, fp16 b) {
    __half2 t(a, b);
    return *reinterpret_cast<uint32_t*>(&t);
}
__device__ __forceinline__ void split1(float v, fp16& h, fp16& l) {
    h = __float2half(v);
    l = __float2half(v - __half2float(h));
}
__device__ __forceinline__ uint4 cvt8(const float* f) {
    return make_uint4(pack_h2(__float2half(f[0]), __float2half(f[1])),
                      pack_h2(__float2half(f[2]), __float2half(f[3])),
                      pack_h2(__float2half(f[4]), __float2half(f[5])),
                      pack_h2(__float2half(f[6]), __float2half(f[7])));
}
__device__ __forceinline__ void split8(const float* f, uint4& hi, uint4& lo) {
    fp16 h[8], l[8];
#pragma unroll
    for (int i = 0; i < 8; ++i) split1(f[i], h[i], l[i]);
    hi = make_uint4(pack_h2(h[0], h[1]), pack_h2(h[2], h[3]),
                    pack_h2(h[4], h[5]), pack_h2(h[6], h[7]));
    lo = make_uint4(pack_h2(l[0], l[1]), pack_h2(l[2], l[3]),
                    pack_h2(l[4], l[5]), pack_h2(l[6], l[7]));
}

// ---------------- prep ----------------
__global__ void prep_kernel(const float* __restrict__ gcnW,
                            const float* __restrict__ wb,
                            const float* __restrict__ gb,
                            const float* __restrict__ bih,
                            const float* __restrict__ bhh,
                            const int* __restrict__ qlc_i32) {
    int idx = blockIdx.x * blockDim.x + threadIdx.x;
    if (idx == 0) {
        int any = 0;
        for (int i = 1; i < 2 * NB; i += 2) any |= qlc_i32[i];
        g_is64 = (any == 0) ? 1 : 0;
    }
    if (idx < 256 * 128) {
        int j = idx >> 7, e = idx & 127;
        float v = (j < 128) ? gcnW[j * 256 + e] : gcnW[(j - 128) * 256 + 128 + e];
        fp16 h, l;
        split1(v, h, l);
        g_Wphi[idx] = h;
        g_Wplo[idx] = l;
    }
    if (idx < 256) g_biasproj[idx] = (idx < 128) ? (wb[idx] + gb[idx]) : 0.f;
    if (idx < G4)  g_bsum[idx] = bih[idx] + bhh[idx];
}

// ---------------- emb -> fp16 (vectorized x8) ----------------
__global__ void cvt_emb_kernel(const float* __restrict__ emb, int total8) {
    int i = blockIdx.x * blockDim.x + threadIdx.x;
    if (i >= total8) return;
    int e0 = i * 8;
    float4 v0 = *reinterpret_cast<const float4*>(emb + e0);
    float4 v1 = *reinterpret_cast<const float4*>(emb + e0 + 4);
    float f[8] = {v0.x, v0.y, v0.z, v0.w, v1.x, v1.y, v1.z, v1.w};
    *reinterpret_cast<uint4*>(g_embhi + e0) = cvt8(f);
}

// ---------------- split all 4 B-weights into fp16 hi/lo ----------------
#define T8_P1 (512 * 256 / 8)
#define T8_P2 (256 * 512 / 8)
#define T8_WI (2048 * 256 / 8)
#define T8_WH (2048 * 256 / 8)
__global__ void split_all_kernel(const float* __restrict__ p1W,
                                 const float* __restrict__ p2W,
                                 const float* __restrict__ Wih,
                                 const float* __restrict__ Whh) {
    int i = blockIdx.x * blockDim.x + threadIdx.x;
    const float* src;
    fp16 *hi, *lo;
    int e0;
    if (i < T8_P1) {
        e0 = i * 8; src = p1W + e0; hi = g_p1hi + e0; lo = g_p1lo + e0;
    } else if (i < T8_P1 + T8_P2) {
        e0 = (i - T8_P1) * 8; src = p2W + e0; hi = g_p2hi + e0; lo = g_p2lo + e0;
    } else if (i < T8_P1 + T8_P2 + T8_WI) {
        e0 = (i - T8_P1 - T8_P2) * 8; src = Wih + e0; hi = g_Wihhi + e0; lo = g_Wihlo + e0;
    } else if (i < T8_P1 + T8_P2 + T8_WI + T8_WH) {
        e0 = (i - T8_P1 - T8_P2 - T8_WI) * 8;
        int row = e0 >> 8, col = e0 & 255;   // Whh: cols 0..255 of ldw=512
        src = Whh + (size_t)row * 512 + col;
        hi = g_Whhhi + e0; lo = g_Whhlo + e0;
    } else return;
    float4 v0 = *reinterpret_cast<const float4*>(src);
    float4 v1 = *reinterpret_cast<const float4*>(src + 4);
    float f[8] = {v0.x, v0.y, v0.z, v0.w, v1.x, v1.y, v1.z, v1.w};
    uint4 h, l;
    split8(f, h, l);
    *reinterpret_cast<uint4*>(hi) = h;
    *reinterpret_cast<uint4*>(lo) = l;
}

// =====================================================================
// proj_mma v3: g_projh[NSYM,256] = fp16(emb @ Wproj^T + bias)
// A fp16 single, B fp16 hi+lo (2-pass). CTA tile 128(M) x 128(N).
// 256 threads = 4Mx2N warps of 32x64. 104KB smem -> 2 CTAs/SM.
// grid = (2 column halves, 1563 row tiles)
// =====================================================================
#define ROWB 272
#define PA_OFF 0
#define PBH_OFF (128 * ROWB)
#define PBL_OFF (2 * 128 * ROWB)
#define PROJ_SMEM (3 * 128 * ROWB)   // 104448

__global__ void __launch_bounds__(256, 2)
proj_mma_kernel() {
    extern __shared__ char sm[];
    const uint32_t sbase = smem_u32(sm);
    const int tid = threadIdx.x;
    const int nhalf = blockIdx.x;           // 0 or 1 -> cols [0,128) or [128,256)
    const int mbase = blockIdx.y * 128;

    // A tile: 128 rows x 128 fp16 = 2048 chunks of 16B
#pragma unroll
    for (int i = 0; i < 8; ++i) {
        int c = tid + i * 256;
        int row = c >> 4, ch = c & 15;
        int grow = mbase + row;
        uint4 h = make_uint4(0, 0, 0, 0);
        if (grow < NSYM)
            h = *reinterpret_cast<const uint4*>(g_embhi + (size_t)grow * 128 + ch * 8);
        *reinterpret_cast<uint4*>(sm + PA_OFF + row * ROWB + ch * 16) = h;
    }
    // B tiles: 128 rows (this N half) x 128 fp16, hi & lo
#pragma unroll
    for (int i = 0; i < 8; ++i) {
        int c = tid + i * 256;
        int row = c >> 4, ch = c & 15;
        int grow = nhalf * 128 + row;
        uint4 h = *reinterpret_cast<const uint4*>(g_Wphi + grow * 128 + ch * 8);
        uint4 l = *reinterpret_cast<const uint4*>(g_Wplo + grow * 128 + ch * 8);
        int off = row * ROWB + ch * 16;
        *reinterpret_cast<uint4*>(sm + PBH_OFF + off) = h;
        *reinterpret_cast<uint4*>(sm + PBL_OFF + off) = l;
    }
    __syncthreads();

    const int warp = tid >> 5, lane = tid & 31;
    const int wm = warp & 3, wn = warp >> 2;   // 4M x 2N
    const int m0 = wm * 32, n0 = wn * 64;

    float acc[2][8][4];
#pragma unroll
    for (int i = 0; i < 2; ++i)
#pragma unroll
        for (int j = 0; j < 8; ++j)
#pragma unroll
            for (int q = 0; q < 4; ++q) acc[i][j][q] = 0.f;

    const int a_row = (lane & 15);
    const int a_kadd = (lane >> 4) << 3;
    const int b_row = ((lane >> 4) << 3) + (lane & 7);
    const int b_kadd = ((lane >> 3) & 1) << 3;

#pragma unroll
    for (int ks = 0; ks < 8; ++ks) {
        const int k0 = ks * 16;
        uint32_t ra[2][4];
#pragma unroll
        for (int mi = 0; mi < 2; ++mi)
            ldmatrix4(sbase + PA_OFF + (m0 + mi * 16 + a_row) * ROWB + (k0 + a_kadd) * 2,
                      ra[mi][0], ra[mi][1], ra[mi][2], ra[mi][3]);
        uint32_t rbh[4][4], rbl[4][4];
#pragma unroll
        for (int np = 0; np < 4; ++np) {
            uint32_t boff = (n0 + np * 16 + b_row) * ROWB + (k0 + b_kadd) * 2;
            ldmatrix4(sbase + PBH_OFF + boff, rbh[np][0], rbh[np][1], rbh[np][2], rbh[np][3]);
            ldmatrix4(sbase + PBL_OFF + boff, rbl[np][0], rbl[np][1], rbl[np][2], rbl[np][3]);
        }
#pragma unroll
        for (int mi = 0; mi < 2; ++mi)
#pragma unroll
            for (int ni = 0; ni < 8; ++ni) {
                mma16816(acc[mi][ni], ra[mi],
                         rbh[ni >> 1][(ni & 1) * 2 + 0], rbh[ni >> 1][(ni & 1) * 2 + 1]);
                mma16816(acc[mi][ni], ra[mi],
                         rbl[ni >> 1][(ni & 1) * 2 + 0], rbl[ni >> 1][(ni & 1) * 2 + 1]);
            }
    }

    const int rbase = mbase + m0;
#pragma unroll
    for (int mi = 0; mi < 2; ++mi) {
#pragma unroll
        for (int ni = 0; ni < 8; ++ni) {
            int gcol = nhalf * 128 + n0 + ni * 8 + (lane & 3) * 2;
            float b0 = g_biasproj[gcol], b1 = g_biasproj[gcol + 1];
            int r0 = rbase + mi * 16 + (lane >> 2);
            int r1 = r0 + 8;
            if (r0 < NSYM)
                *reinterpret_cast<uint32_t*>(g_projh + (size_t)r0 * 256 + gcol) =
                    pack_h2(__float2half(acc[mi][ni][0] + b0), __float2half(acc[mi][ni][1] + b1));
            if (r1 < NSYM)
                *reinterpret_cast<uint32_t*>(g_projh + (size_t)r1 * 256 + gcol) =
                    pack_h2(__float2half(acc[mi][ni][2] + b0), __float2half(acc[mi][ni][3] + b1));
        }
    }
}

// =====================================================================
// generic 2-pass HMMA GEMM: C[M,N] = A[M,K](fp16) @ (Bhi+Blo)[N,K]^T
// =====================================================================
#define KROWB 144
#define HG_A  0
#define HG_BH (128 * KROWB)
#define HG_BL (2 * 128 * KROWB)
#define HG_SMEM (3 * 128 * KROWB)   // 55296

__global__ void __launch_bounds__(256, 2)
hgemm2(int M, int N, int K,
       const fp16* __restrict__ A,
       const fp16* __restrict__ Bhi, const fp16* __restrict__ Blo,
       const float* __restrict__ bias, const float* __restrict__ addMat,
       float* __restrict__ C, fp16* __restrict__ Chi, int doRelu) {
    extern __shared__ char sm[];
    const uint32_t sbase = smem_u32(sm);
    const int tid = threadIdx.x;
    const int mtile = blockIdx.y * 128, ntile = blockIdx.x * 128;

    const int warp = tid >> 5, lane = tid & 31;
    const int wm = warp & 3, wn = warp >> 2;
    const int m0 = wm * 32, n0 = wn * 64;

    float acc[2][8][4];
#pragma unroll
    for (int i = 0; i < 2; ++i)
#pragma unroll
        for (int j = 0; j < 8; ++j)
#pragma unroll
            for (int q = 0; q < 4; ++q) acc[i][j][q] = 0.f;

    const int a_row = (lane & 15);
    const int a_kadd = (lane >> 4) << 3;
    const int b_row = ((lane >> 4) << 3) + (lane & 7);
    const int b_kadd = ((lane >> 3) & 1) << 3;

    for (int kc = 0; kc < K; kc += 64) {
        // A: 128 rows x 64 fp16 = 1024 chunks of 8 fp16
#pragma unroll
        for (int i = 0; i < 4; ++i) {
            int c = tid + i * 256;
            int row = c >> 3, ch = c & 7;
            int gk = kc + ch * 8;
            int grow = mtile + row;
            uint4 h = make_uint4(0, 0, 0, 0);
            if (grow < M)
                h = *reinterpret_cast<const uint4*>(A + (size_t)grow * K + gk);
            *reinterpret_cast<uint4*>(sm + HG_A + row * KROWB + ch * 16) = h;
        }
        // B hi/lo: 1024 chunks each
#pragma unroll
        for (int i = 0; i < 4; ++i) {
            int c = tid + i * 256;
            int row = c >> 3, ch = c & 7;
            int gk = kc + ch * 8;
            int grow = ntile + row;
            uint4 h = *reinterpret_cast<const uint4*>(Bhi + (size_t)grow * K + gk);
            uint4 l = *reinterpret_cast<const uint4*>(Blo + (size_t)grow * K + gk);
            int off = row * KROWB + ch * 16;
            *reinterpret_cast<uint4*>(sm + HG_BH + off) = h;
            *reinterpret_cast<uint4*>(sm + HG_BL + off) = l;
        }
        __syncthreads();

#pragma unroll
        for (int ks = 0; ks < 4; ++ks) {
            const int k0 = ks * 16;
            uint32_t ra[2][4];
#pragma unroll
            for (int mi = 0; mi < 2; ++mi)
                ldmatrix4(sbase + HG_A + (m0 + mi * 16 + a_row) * KROWB + (k0 + a_kadd) * 2,
                          ra[mi][0], ra[mi][1], ra[mi][2], ra[mi][3]);
            uint32_t rbh[4][4], rbl[4][4];
#pragma unroll
            for (int np = 0; np < 4; ++np) {
                uint32_t boff = (n0 + np * 16 + b_row) * KROWB + (k0 + b_kadd) * 2;
                ldmatrix4(sbase + HG_BH + boff, rbh[np][0], rbh[np][1], rbh[np][2], rbh[np][3]);
                ldmatrix4(sbase + HG_BL + boff, rbl[np][0], rbl[np][1], rbl[np][2], rbl[np][3]);
            }
#pragma unroll
            for (int mi = 0; mi < 2; ++mi)
#pragma unroll
                for (int ni = 0; ni < 8; ++ni) {
                    mma16816(acc[mi][ni], ra[mi],
                             rbh[ni >> 1][(ni & 1) * 2 + 0], rbh[ni >> 1][(ni & 1) * 2 + 1]);
                    mma16816(acc[mi][ni], ra[mi],
                             rbl[ni >> 1][(ni & 1) * 2 + 0], rbl[ni >> 1][(ni & 1) * 2 + 1]);
                }
        }
        __syncthreads();
    }

#pragma unroll
    for (int mi = 0; mi < 2; ++mi) {
#pragma unroll
        for (int ni = 0; ni < 8; ++ni) {
            int col = ntile + n0 + ni * 8 + (lane & 3) * 2;
            float b0 = bias ? bias[col] : 0.f;
            float b1 = bias ? bias[col + 1] : 0.f;
#pragma unroll
            for (int half = 0; half < 2; ++half) {
                int r = mtile + m0 + mi * 16 + (lane >> 2) + half * 8;
                if (r >= M) continue;
                float vx = acc[mi][ni][half * 2 + 0] + b0;
                float vy = acc[mi][ni][half * 2 + 1] + b1;
                if (addMat) {
                    vx += addMat[(size_t)r * N + col];
                    vy += addMat[(size_t)r * N + col + 1];
                }
                if (doRelu) { vx = fmaxf(vx, 0.f); vy = fmaxf(vy, 0.f); }
                if (C)
                    *reinterpret_cast<float2*>(C + (size_t)r * N + col) = make_float2(vx, vy);
                if (Chi)
                    *reinterpret_cast<uint32_t*>(Chi + (size_t)r * N + col) =
                        pack_h2(__float2half(vx), __float2half(vy));
            }
        }
    }
}

// ---------------- neighbor encoder (fp16 gather) ----------------
__global__ void __launch_bounds__(128)
neighbor_kernel(const void* qlc, const void* qrc, const void* slc, const void* src) {
    __shared__ int sidx[2 * NB];
    int b = blockIdx.x;
    const void* conn;
    int node, off;
    if (b < BQ)                { conn = qlc; node = b;                off = node * DM; }
    else if (b < 2 * BQ)       { conn = qrc; node = b - BQ;           off = node * DM + 128; }
    else if (b < 2 * BQ + FEW) { conn = slc; node = b - 2 * BQ;       off = (BQ + node) * DM; }
    else                       { conn = src; node = b - 2 * BQ - FEW; off = (BQ + node) * DM + 128; }

    int tid = threadIdx.x;
    size_t base = (size_t)node * (2 * NB);
    if (g_is64) {
        const long long* p = (const long long*)conn;
        for (int t = tid; t < 2 * NB; t += 128) sidx[t] = (int)p[base + t];
    } else {
        const int* p = (const int*)conn;
        for (int t = tid; t < 2 * NB; t += 128) sidx[t] = p[base + t];
    }
    __syncthreads();

    const fp16* __restrict__ proj = g_projh;
    float m = -INFINITY;
#pragma unroll 2
    for (int k = 0; k < NB; ++k) {
        int rel = sidx[2 * k], ent = sidx[2 * k + 1];
        if (rel == PADID || ent == PADID) continue;
        float v = __half2float(proj[(size_t)rel * 256 + tid]) +
                  __half2float(proj[(size_t)ent * 256 + 128 + tid]);
        v = (v > 0.f) ? v : 0.1f * v;
        m = fmaxf(m, v);
    }
    float t = tanhf(m);
    g_xcat[off + tid] = t;
    g_xcathi[off + tid] = __float2half(t);
}

// ---------------- layernorm ----------------
__global__ void ln_kernel(const float* __restrict__ lg, const float* __restrict__ lb) {
    __shared__ float red[256];
    int row = blockIdx.x, t = threadIdx.x;
    float v = g_oenc[row * DM + t];
    red[t] = v;
    __syncthreads();
    for (int s = 128; s > 0; s >>= 1) { if (t < s) red[t] += red[t + s]; __syncthreads(); }
    float mu = red[0] * (1.f / 256.f);
    __syncthreads();
    float d = v - mu;
    red[t] = d * d;
    __syncthreads();
    for (int s = 128; s > 0; s >>= 1) { if (t < s) red[t] += red[t + s]; __syncthreads(); }
    float var = red[0] * (1.f / 256.f);
    float o = d * rsqrtf(var + 1e-5f) * lg[t] + lb[t];
    g_enc[row * DM + t] = o;
    g_enchi[row * DM + t] = __float2half(o);
}

// ---------------- support_g mean (tiny) ----------------
__global__ void mean_kernel() {
    int t = threadIdx.x;
    float s = 0.f;
    for (int r = 0; r < FEW; ++r) s += g_enc[(BQ + r) * DM + t];
    g_support[t] = s * (1.f / FEW);
}

// ---------------- sconst: warp per gate, coalesced ----------------
__global__ void sconst_kernel(const float* __restrict__ Whh) {
    int gidx = (blockIdx.x * blockDim.x + threadIdx.x) >> 5;
    int lane = threadIdx.x & 31;
    if (gidx >= G4) return;
    float s = 0.f;
    for (int i = lane; i < DM; i += 32)
        s += g_support[i] * Whh[(size_t)gidx * 512 + 256 + i];
#pragma unroll
    for (int o = 16; o > 0; o >>= 1) s += __shfl_down_sync(0xffffffffu, s, o);
    if (lane == 0) g_sconst[gidx] = s;
}

// ---------------- LSTM elementwise step ----------------
__device__ __forceinline__ float sigm(float x) { return 1.f / (1.f + expf(-x)); }

__global__ void lstm_kernel(const float* __restrict__ G, int firstStep) {
    int idx = blockIdx.x * blockDim.x + threadIdx.x;
    if (idx >= BQ * HID) return;
    int n = idx >> 9, j = idx & 511;
    const float* g = G + (size_t)n * G4;
    float gi = g[j], gf = g[512 + j], gg = g[1024 + j], go = g[1536 + j];
    float c  = firstStep ? 0.f : g_c[idx];
    float cn = sigm(gf) * c + sigm(gi) * tanhf(gg);
    g_c[idx] = cn;
    if (j < DM) {
        float hv = g_enc[n * DM + j] + sigm(go) * tanhf(cn);
        g_h[n * DM + j] = hv;
        g_hhi[n * DM + j] = __float2half(hv);
    }
}

// ---------------- final dot ----------------
__global__ void final_kernel(float* __restrict__ out) {
    int n = (blockIdx.x * blockDim.x + threadIdx.x) >> 5;
    int lane = threadIdx.x & 31;
    if (n >= BQ) return;
    float s = 0.f;
    for (int i = lane; i < DM; i += 32)
        s += g_h[n * DM + i] * g_support[i];
#pragma unroll
    for (int o = 16; o > 0; o >>= 1) s += __shfl_down_sync(0xffffffffu, s, o);
    if (lane == 0) out[n] = s;
}

// ---------------- launch ----------------
extern "C" void kernel_launch(void* const* d_in, const int* in_sizes, int n_in,
                              void* d_out, int out_size) {
    const void* qlc = d_in[0];
    const void* qrc = d_in[1];
    const void* slc = d_in[2];
    const void* src = d_in[3];
    const float* emb  = (const float*)d_in[8];
    const float* gcnW = (const float*)d_in[9];
    const float* wb   = (const float*)d_in[10];
    const float* gb   = (const float*)d_in[11];
    const float* p1W  = (const float*)d_in[12];
    const float* p1b  = (const float*)d_in[13];
    const float* p2W  = (const float*)d_in[14];
    const float* p2b  = (const float*)d_in[15];
    const float* lng  = (const float*)d_in[16];
    const float* lnb  = (const float*)d_in[17];
    const float* Wih  = (const float*)d_in[18];
    const float* Whh  = (const float*)d_in[19];
    const float* bih  = (const float*)d_in[20];
    const float* bhh  = (const float*)d_in[21];

    fp16 *p1hi, *p1lo, *p2hi, *p2lo, *Wihhi, *Wihlo, *Whhhi, *Whhlo;
    fp16 *xcathi, *henchi, *enchi, *hhi;
    float *xcat, *oenc, *sconst, *qWihb, *gates, *bsum;
    cudaGetSymbolAddress((void**)&p1hi,  g_p1hi);
    cudaGetSymbolAddress((void**)&p1lo,  g_p1lo);
    cudaGetSymbolAddress((void**)&p2hi,  g_p2hi);
    cudaGetSymbolAddress((void**)&p2lo,  g_p2lo);
    cudaGetSymbolAddress((void**)&Wihhi, g_Wihhi);
    cudaGetSymbolAddress((void**)&Wihlo, g_Wihlo);
    cudaGetSymbolAddress((void**)&Whhhi, g_Whhhi);
    cudaGetSymbolAddress((void**)&Whhlo, g_Whhlo);
    cudaGetSymbolAddress((void**)&xcathi, g_xcathi);
    cudaGetSymbolAddress((void**)&henchi, g_henchi);
    cudaGetSymbolAddress((void**)&enchi,  g_enchi);
    cudaGetSymbolAddress((void**)&hhi,    g_hhi);
    cudaGetSymbolAddress((void**)&xcat,   g_xcat);
    cudaGetSymbolAddress((void**)&oenc,   g_oenc);
    cudaGetSymbolAddress((void**)&sconst, g_sconst);
    cudaGetSymbolAddress((void**)&qWihb,  g_qWihb);
    cudaGetSymbolAddress((void**)&gates,  g_gates);
    cudaGetSymbolAddress((void**)&bsum,   g_bsum);

    prep_kernel<<<128, 256>>>(gcnW, wb, gb, bih, bhh, (const int*)qlc);
    cvt_emb_kernel<<<(NSYM * 16 + 255) / 256, 256>>>(emb, NSYM * 16);
    split_all_kernel<<<(T8_P1 + T8_P2 + T8_WI + T8_WH + 255) / 256, 256>>>(p1W, p2W, Wih, Whh);

    cudaFuncSetAttribute(proj_mma_kernel,
                         cudaFuncAttributeMaxDynamicSharedMemorySize, PROJ_SMEM);
    proj_mma_kernel<<<dim3(2, (NSYM + 127) / 128), 256, PROJ_SMEM>>>();

    neighbor_kernel<<<2 * BQ + 2 * FEW, 128>>>(qlc, qrc, slc, src);

    cudaFuncSetAttribute(hgemm2,
                         cudaFuncAttributeMaxDynamicSharedMemorySize, HG_SMEM);

    // henc = relu(xcat@p1W^T + p1b) -> fp16 only
    hgemm2<<<dim3(512 / 128, (NROWS + 127) / 128), 256, HG_SMEM>>>(
        NROWS, 512, 256, xcathi, p1hi, p1lo, p1b, nullptr, nullptr, henchi, 1);
    // oenc = henc@p2W^T + p2b + xcat
    hgemm2<<<dim3(256 / 128, (NROWS + 127) / 128), 256, HG_SMEM>>>(
        NROWS, 256, 512, henchi, p2hi, p2lo, p2b, xcat, oenc, nullptr, 0);
    ln_kernel<<<NROWS, 256>>>(lng, lnb);

    mean_kernel<<<1, 256>>>();
    sconst_kernel<<<G4 * 32 / 256, 256>>>(Whh);

    // qWihb = enc@Wih^T + (b_ih + b_hh)
    hgemm2<<<dim3(G4 / 128, BQ / 128), 256, HG_SMEM>>>(
        BQ, G4, 256, enchi, Wihhi, Wihlo, bsum, nullptr, qWihb, nullptr, 0);

    lstm_kernel<<<(BQ * HID + 255) / 256, 256>>>(qWihb, 1);

    for (int s = 1; s < 4; ++s) {
        hgemm2<<<dim3(G4 / 128, BQ / 128), 256, HG_SMEM>>>(
            BQ, G4, 256, hhi, Whhhi, Whhlo, sconst, qWihb, gates, nullptr, 0);
        lstm_kernel<<<(BQ * HID + 255) / 256, 256>>>(gates, 0);
    }

    final_kernel<<<(BQ * 32 + 255) / 256, 256>>>((float*)d_out);
}

// round 9
// speedup vs baseline: 2.2080x; 1.2368x over previous
#include <cuda_runtime.h>
#include <cuda_fp16.h>
#include <cstdint>
#include <math.h>

// ---------------- problem constants ----------------
#define NSYM   200001
#define PADID  200000
#define BQ     1024
#define FEW    5
#define NB     200
#define DM     256
#define DI     512
#define HID    512
#define G4     2048
#define NROWS  (BQ + FEW)

typedef __half fp16;

// ---------------- device scratch ----------------
__device__ fp16  g_projh[(size_t)NSYM * 256];
__device__ fp16  g_embh[(size_t)NSYM * 128];
__device__ fp16  g_Wph[256 * 128];
__device__ fp16  g_p1h[512 * 256];
__device__ fp16  g_p2h[256 * 512];
__device__ fp16  g_Wihh[2048 * 256];
__device__ fp16  g_Whhh[2048 * 256];
__device__ float g_biasproj[256];
__device__ float g_bsum[G4];
__device__ float g_xcat[NROWS * DM];
__device__ fp16  g_xcath[NROWS * DM];
__device__ fp16  g_hench[NROWS * DI];
__device__ float g_oenc[NROWS * DM];
__device__ float g_enc[NROWS * DM];
__device__ fp16  g_ench[NROWS * DM];
__device__ float g_support[DM];
__device__ float g_sconst[G4];
__device__ float g_qWihb[BQ * G4];
__device__ float g_gates[BQ * G4];
__device__ float g_h[BQ * DM];
__device__ fp16  g_hh[BQ * DM];
__device__ float g_c[BQ * HID];
__device__ int   g_is64;

// ---------------- helpers ----------------
__device__ __forceinline__ uint32_t smem_u32(const void* p) {
    uint32_t a;
    asm("{ .reg .u64 t; cvta.to.shared.u64 t, %1; cvt.u32.u64 %0, t; }" : "=r"(a) : "l"(p));
    return a;
}
__device__ __forceinline__ void ldmatrix4(uint32_t addr, uint32_t& r0, uint32_t& r1,
                                          uint32_t& r2, uint32_t& r3) {
    asm volatile("ldmatrix.sync.aligned.m8n8.x4.shared.b16 {%0,%1,%2,%3}, [%4];"
                 : "=r"(r0), "=r"(r1), "=r"(r2), "=r"(r3) : "r"(addr));
}
__device__ __forceinline__ void mma16816(float* d, const uint32_t* a,
                                         uint32_t b0, uint32_t b1) {
    asm volatile(
        "mma.sync.aligned.m16n8k16.row.col.f32.f16.f16.f32 "
        "{%0,%1,%2,%3}, {%4,%5,%6,%7}, {%8,%9}, {%0,%1,%2,%3};"
        : "+f"(d[0]), "+f"(d[1]), "+f"(d[2]), "+f"(d[3])
        : "r"(a[0]), "r"(a[1]), "r"(a[2]), "r"(a[3]), "r"(b0), "r"(b1));
}
__device__ __forceinline__ uint32_t pack_h2(fp16 a, fp16 b) {
    __half2 t(a, b);
    return *reinterpret_cast<uint32_t*>(&t);
}
__device__ __forceinline__ uint4 cvt8(const float* f) {
    return make_uint4(pack_h2(__float2half(f[0]), __float2half(f[1])),
                      pack_h2(__float2half(f[2]), __float2half(f[3])),
                      pack_h2(__float2half(f[4]), __float2half(f[5])),
                      pack_h2(__float2half(f[6]), __float2half(f[7])));
}

// ---------------- prep ----------------
__global__ void prep_kernel(const float* __restrict__ gcnW,
                            const float* __restrict__ wb,
                            const float* __restrict__ gb,
                            const float* __restrict__ bih,
                            const float* __restrict__ bhh,
                            const int* __restrict__ qlc_i32) {
    int idx = blockIdx.x * blockDim.x + threadIdx.x;
    if (idx == 0) {
        int any = 0;
        for (int i = 1; i < 2 * NB; i += 2) any |= qlc_i32[i];
        g_is64 = (any == 0) ? 1 : 0;
    }
    if (idx < 256 * 128) {
        int j = idx >> 7, e = idx & 127;
        float v = (j < 128) ? gcnW[j * 256 + e] : gcnW[(j - 128) * 256 + 128 + e];
        g_Wph[idx] = __float2half(v);
    }
    if (idx < 256) g_biasproj[idx] = (idx < 128) ? (wb[idx] + gb[idx]) : 0.f;
    if (idx < G4)  g_bsum[idx] = bih[idx] + bhh[idx];
}

// ---------------- emb -> fp16 ----------------
__global__ void cvt_emb_kernel(const float* __restrict__ emb, int total8) {
    int i = blockIdx.x * blockDim.x + threadIdx.x;
    if (i >= total8) return;
    int e0 = i * 8;
    float4 v0 = *reinterpret_cast<const float4*>(emb + e0);
    float4 v1 = *reinterpret_cast<const float4*>(emb + e0 + 4);
    float f[8] = {v0.x, v0.y, v0.z, v0.w, v1.x, v1.y, v1.z, v1.w};
    *reinterpret_cast<uint4*>(g_embh + e0) = cvt8(f);
}

// ---------------- convert all 4 B-weights to fp16 (one kernel) ----------------
#define T8_P1 (512 * 256 / 8)
#define T8_P2 (256 * 512 / 8)
#define T8_WI (2048 * 256 / 8)
#define T8_WH (2048 * 256 / 8)
__global__ void cvt_all_kernel(const float* __restrict__ p1W,
                               const float* __restrict__ p2W,
                               const float* __restrict__ Wih,
                               const float* __restrict__ Whh) {
    int i = blockIdx.x * blockDim.x + threadIdx.x;
    const float* src;
    fp16* dst;
    int e0;
    if (i < T8_P1) {
        e0 = i * 8; src = p1W + e0; dst = g_p1h + e0;
    } else if (i < T8_P1 + T8_P2) {
        e0 = (i - T8_P1) * 8; src = p2W + e0; dst = g_p2h + e0;
    } else if (i < T8_P1 + T8_P2 + T8_WI) {
        e0 = (i - T8_P1 - T8_P2) * 8; src = Wih + e0; dst = g_Wihh + e0;
    } else if (i < T8_P1 + T8_P2 + T8_WI + T8_WH) {
        e0 = (i - T8_P1 - T8_P2 - T8_WI) * 8;
        int row = e0 >> 8, col = e0 & 255;   // Whh: cols 0..255 of ldw=512
        src = Whh + (size_t)row * 512 + col;
        dst = g_Whhh + e0;
    } else return;
    float4 v0 = *reinterpret_cast<const float4*>(src);
    float4 v1 = *reinterpret_cast<const float4*>(src + 4);
    float f[8] = {v0.x, v0.y, v0.z, v0.w, v1.x, v1.y, v1.z, v1.w};
    *reinterpret_cast<uint4*>(dst) = cvt8(f);
}

// =====================================================================
// proj_mma v4: g_projh[NSYM,256] = fp16(emb @ Wproj^T + bias)
// plain fp16 single-pass. CTA tile 128(M) x 128(N), 256 threads
// (4Mx2N warps of 32x64), 68KB smem, 2 CTAs/SM.
// grid = (2 column halves, 1563 row tiles)
// =====================================================================
#define ROWB 272
#define PA_OFF 0
#define PB_OFF (128 * ROWB)
#define PROJ_SMEM (2 * 128 * ROWB)   // 69632

__global__ void __launch_bounds__(256, 2)
proj_mma_kernel() {
    extern __shared__ char sm[];
    const uint32_t sbase = smem_u32(sm);
    const int tid = threadIdx.x;
    const int nhalf = blockIdx.x;
    const int mbase = blockIdx.y * 128;

    // A tile: 128 rows x 128 fp16 = 2048 chunks of 16B
#pragma unroll
    for (int i = 0; i < 8; ++i) {
        int c = tid + i * 256;
        int row = c >> 4, ch = c & 15;
        int grow = mbase + row;
        uint4 h = make_uint4(0, 0, 0, 0);
        if (grow < NSYM)
            h = *reinterpret_cast<const uint4*>(g_embh + (size_t)grow * 128 + ch * 8);
        *reinterpret_cast<uint4*>(sm + PA_OFF + row * ROWB + ch * 16) = h;
    }
    // B tile: 128 rows (this N half) x 128 fp16
#pragma unroll
    for (int i = 0; i < 8; ++i) {
        int c = tid + i * 256;
        int row = c >> 4, ch = c & 15;
        int grow = nhalf * 128 + row;
        uint4 h = *reinterpret_cast<const uint4*>(g_Wph + grow * 128 + ch * 8);
        *reinterpret_cast<uint4*>(sm + PB_OFF + row * ROWB + ch * 16) = h;
    }
    __syncthreads();

    const int warp = tid >> 5, lane = tid & 31;
    const int wm = warp & 3, wn = warp >> 2;
    const int m0 = wm * 32, n0 = wn * 64;

    float acc[2][8][4];
#pragma unroll
    for (int i = 0; i < 2; ++i)
#pragma unroll
        for (int j = 0; j < 8; ++j)
#pragma unroll
            for (int q = 0; q < 4; ++q) acc[i][j][q] = 0.f;

    const int a_row = (lane & 15);
    const int a_kadd = (lane >> 4) << 3;
    const int b_row = ((lane >> 4) << 3) + (lane & 7);
    const int b_kadd = ((lane >> 3) & 1) << 3;

#pragma unroll
    for (int ks = 0; ks < 8; ++ks) {
        const int k0 = ks * 16;
        uint32_t ra[2][4];
#pragma unroll
        for (int mi = 0; mi < 2; ++mi)
            ldmatrix4(sbase + PA_OFF + (m0 + mi * 16 + a_row) * ROWB + (k0 + a_kadd) * 2,
                      ra[mi][0], ra[mi][1], ra[mi][2], ra[mi][3]);
        uint32_t rb[4][4];
#pragma unroll
        for (int np = 0; np < 4; ++np)
            ldmatrix4(sbase + PB_OFF + (n0 + np * 16 + b_row) * ROWB + (k0 + b_kadd) * 2,
                      rb[np][0], rb[np][1], rb[np][2], rb[np][3]);
#pragma unroll
        for (int mi = 0; mi < 2; ++mi)
#pragma unroll
            for (int ni = 0; ni < 8; ++ni)
                mma16816(acc[mi][ni], ra[mi],
                         rb[ni >> 1][(ni & 1) * 2 + 0], rb[ni >> 1][(ni & 1) * 2 + 1]);
    }

    const int rbase = mbase + m0;
#pragma unroll
    for (int mi = 0; mi < 2; ++mi) {
#pragma unroll
        for (int ni = 0; ni < 8; ++ni) {
            int gcol = nhalf * 128 + n0 + ni * 8 + (lane & 3) * 2;
            float b0 = g_biasproj[gcol], b1 = g_biasproj[gcol + 1];
            int r0 = rbase + mi * 16 + (lane >> 2);
            int r1 = r0 + 8;
            if (r0 < NSYM)
                *reinterpret_cast<uint32_t*>(g_projh + (size_t)r0 * 256 + gcol) =
                    pack_h2(__float2half(acc[mi][ni][0] + b0), __float2half(acc[mi][ni][1] + b1));
            if (r1 < NSYM)
                *reinterpret_cast<uint32_t*>(g_projh + (size_t)r1 * 256 + gcol) =
                    pack_h2(__float2half(acc[mi][ni][2] + b0), __float2half(acc[mi][ni][3] + b1));
        }
    }
}

// =====================================================================
// plain fp16 HMMA GEMM: C[M,N] = A[M,K] @ B[N,K]^T (+bias,+add,relu)
// CTA tile 128x128, K-chunk 64, 256 threads.
// =====================================================================
#define KROWB 144
#define HG_A  0
#define HG_B  (128 * KROWB)
#define HG_SMEM (2 * 128 * KROWB)   // 36864

__global__ void __launch_bounds__(256, 2)
hgemm1(int M, int N, int K,
       const fp16* __restrict__ A, const fp16* __restrict__ B,
       const float* __restrict__ bias, const float* __restrict__ addMat,
       float* __restrict__ C, fp16* __restrict__ Chi, int doRelu) {
    extern __shared__ char sm[];
    const uint32_t sbase = smem_u32(sm);
    const int tid = threadIdx.x;
    const int mtile = blockIdx.y * 128, ntile = blockIdx.x * 128;

    const int warp = tid >> 5, lane = tid & 31;
    const int wm = warp & 3, wn = warp >> 2;
    const int m0 = wm * 32, n0 = wn * 64;

    float acc[2][8][4];
#pragma unroll
    for (int i = 0; i < 2; ++i)
#pragma unroll
        for (int j = 0; j < 8; ++j)
#pragma unroll
            for (int q = 0; q < 4; ++q) acc[i][j][q] = 0.f;

    const int a_row = (lane & 15);
    const int a_kadd = (lane >> 4) << 3;
    const int b_row = ((lane >> 4) << 3) + (lane & 7);
    const int b_kadd = ((lane >> 3) & 1) << 3;

    for (int kc = 0; kc < K; kc += 64) {
#pragma unroll
        for (int i = 0; i < 4; ++i) {
            int c = tid + i * 256;
            int row = c >> 3, ch = c & 7;
            int gk = kc + ch * 8;
            int grow = mtile + row;
            uint4 h = make_uint4(0, 0, 0, 0);
            if (grow < M)
                h = *reinterpret_cast<const uint4*>(A + (size_t)grow * K + gk);
            *reinterpret_cast<uint4*>(sm + HG_A + row * KROWB + ch * 16) = h;
        }
#pragma unroll
        for (int i = 0; i < 4; ++i) {
            int c = tid + i * 256;
            int row = c >> 3, ch = c & 7;
            int gk = kc + ch * 8;
            int grow = ntile + row;
            uint4 h = *reinterpret_cast<const uint4*>(B + (size_t)grow * K + gk);
            *reinterpret_cast<uint4*>(sm + HG_B + row * KROWB + ch * 16) = h;
        }
        __syncthreads();

#pragma unroll
        for (int ks = 0; ks < 4; ++ks) {
            const int k0 = ks * 16;
            uint32_t ra[2][4];
#pragma unroll
            for (int mi = 0; mi < 2; ++mi)
                ldmatrix4(sbase + HG_A + (m0 + mi * 16 + a_row) * KROWB + (k0 + a_kadd) * 2,
                          ra[mi][0], ra[mi][1], ra[mi][2], ra[mi][3]);
            uint32_t rb[4][4];
#pragma unroll
            for (int np = 0; np < 4; ++np)
                ldmatrix4(sbase + HG_B + (n0 + np * 16 + b_row) * KROWB + (k0 + b_kadd) * 2,
                          rb[np][0], rb[np][1], rb[np][2], rb[np][3]);
#pragma unroll
            for (int mi = 0; mi < 2; ++mi)
#pragma unroll
                for (int ni = 0; ni < 8; ++ni)
                    mma16816(acc[mi][ni], ra[mi],
                             rb[ni >> 1][(ni & 1) * 2 + 0], rb[ni >> 1][(ni & 1) * 2 + 1]);
        }
        __syncthreads();
    }

#pragma unroll
    for (int mi = 0; mi < 2; ++mi) {
#pragma unroll
        for (int ni = 0; ni < 8; ++ni) {
            int col = ntile + n0 + ni * 8 + (lane & 3) * 2;
            float b0 = bias ? bias[col] : 0.f;
            float b1 = bias ? bias[col + 1] : 0.f;
#pragma unroll
            for (int half = 0; half < 2; ++half) {
                int r = mtile + m0 + mi * 16 + (lane >> 2) + half * 8;
                if (r >= M) continue;
                float vx = acc[mi][ni][half * 2 + 0] + b0;
                float vy = acc[mi][ni][half * 2 + 1] + b1;
                if (addMat) {
                    vx += addMat[(size_t)r * N + col];
                    vy += addMat[(size_t)r * N + col + 1];
                }
                if (doRelu) { vx = fmaxf(vx, 0.f); vy = fmaxf(vy, 0.f); }
                if (C)
                    *reinterpret_cast<float2*>(C + (size_t)r * N + col) = make_float2(vx, vy);
                if (Chi)
                    *reinterpret_cast<uint32_t*>(Chi + (size_t)r * N + col) =
                        pack_h2(__float2half(vx), __float2half(vy));
            }
        }
    }
}

// ---------------- neighbor encoder (fp16 gather) ----------------
__global__ void __launch_bounds__(128)
neighbor_kernel(const void* qlc, const void* qrc, const void* slc, const void* src) {
    __shared__ int sidx[2 * NB];
    int b = blockIdx.x;
    const void* conn;
    int node, off;
    if (b < BQ)                { conn = qlc; node = b;                off = node * DM; }
    else if (b < 2 * BQ)       { conn = qrc; node = b - BQ;           off = node * DM + 128; }
    else if (b < 2 * BQ + FEW) { conn = slc; node = b - 2 * BQ;       off = (BQ + node) * DM; }
    else                       { conn = src; node = b - 2 * BQ - FEW; off = (BQ + node) * DM + 128; }

    int tid = threadIdx.x;
    size_t base = (size_t)node * (2 * NB);
    if (g_is64) {
        const long long* p = (const long long*)conn;
        for (int t = tid; t < 2 * NB; t += 128) sidx[t] = (int)p[base + t];
    } else {
        const int* p = (const int*)conn;
        for (int t = tid; t < 2 * NB; t += 128) sidx[t] = p[base + t];
    }
    __syncthreads();

    const fp16* __restrict__ proj = g_projh;
    float m = -INFINITY;
#pragma unroll 2
    for (int k = 0; k < NB; ++k) {
        int rel = sidx[2 * k], ent = sidx[2 * k + 1];
        if (rel == PADID || ent == PADID) continue;
        float v = __half2float(proj[(size_t)rel * 256 + tid]) +
                  __half2float(proj[(size_t)ent * 256 + 128 + tid]);
        v = (v > 0.f) ? v : 0.1f * v;
        m = fmaxf(m, v);
    }
    float t = tanhf(m);
    g_xcat[off + tid] = t;
    g_xcath[off + tid] = __float2half(t);
}

// ---------------- layernorm ----------------
__global__ void ln_kernel(const float* __restrict__ lg, const float* __restrict__ lb) {
    __shared__ float red[256];
    int row = blockIdx.x, t = threadIdx.x;
    float v = g_oenc[row * DM + t];
    red[t] = v;
    __syncthreads();
    for (int s = 128; s > 0; s >>= 1) { if (t < s) red[t] += red[t + s]; __syncthreads(); }
    float mu = red[0] * (1.f / 256.f);
    __syncthreads();
    float d = v - mu;
    red[t] = d * d;
    __syncthreads();
    for (int s = 128; s > 0; s >>= 1) { if (t < s) red[t] += red[t + s]; __syncthreads(); }
    float var = red[0] * (1.f / 256.f);
    float o = d * rsqrtf(var + 1e-5f) * lg[t] + lb[t];
    g_enc[row * DM + t] = o;
    g_ench[row * DM + t] = __float2half(o);
}

// ---------------- support_g mean ----------------
__global__ void mean_kernel() {
    int t = threadIdx.x;
    float s = 0.f;
    for (int r = 0; r < FEW; ++r) s += g_enc[(BQ + r) * DM + t];
    g_support[t] = s * (1.f / FEW);
}

// ---------------- sconst: warp per gate, coalesced ----------------
__global__ void sconst_kernel(const float* __restrict__ Whh) {
    int gidx = (blockIdx.x * blockDim.x + threadIdx.x) >> 5;
    int lane = threadIdx.x & 31;
    if (gidx >= G4) return;
    float s = 0.f;
    for (int i = lane; i < DM; i += 32)
        s += g_support[i] * Whh[(size_t)gidx * 512 + 256 + i];
#pragma unroll
    for (int o = 16; o > 0; o >>= 1) s += __shfl_down_sync(0xffffffffu, s, o);
    if (lane == 0) g_sconst[gidx] = s;
}

// ---------------- LSTM elementwise step ----------------
__device__ __forceinline__ float sigm(float x) { return 1.f / (1.f + expf(-x)); }

__global__ void lstm_kernel(const float* __restrict__ G, int firstStep) {
    int idx = blockIdx.x * blockDim.x + threadIdx.x;
    if (idx >= BQ * HID) return;
    int n = idx >> 9, j = idx & 511;
    const float* g = G + (size_t)n * G4;
    float gi = g[j], gf = g[512 + j], gg = g[1024 + j], go = g[1536 + j];
    float c  = firstStep ? 0.f : g_c[idx];
    float cn = sigm(gf) * c + sigm(gi) * tanhf(gg);
    g_c[idx] = cn;
    if (j < DM) {
        float hv = g_enc[n * DM + j] + sigm(go) * tanhf(cn);
        g_h[n * DM + j] = hv;
        g_hh[n * DM + j] = __float2half(hv);
    }
}

// ---------------- final dot ----------------
__global__ void final_kernel(float* __restrict__ out) {
    int n = (blockIdx.x * blockDim.x + threadIdx.x) >> 5;
    int lane = threadIdx.x & 31;
    if (n >= BQ) return;
    float s = 0.f;
    for (int i = lane; i < DM; i += 32)
        s += g_h[n * DM + i] * g_support[i];
#pragma unroll
    for (int o = 16; o > 0; o >>= 1) s += __shfl_down_sync(0xffffffffu, s, o);
    if (lane == 0) out[n] = s;
}

// ---------------- launch ----------------
extern "C" void kernel_launch(void* const* d_in, const int* in_sizes, int n_in,
                              void* d_out, int out_size) {
    const void* qlc = d_in[0];
    const void* qrc = d_in[1];
    const void* slc = d_in[2];
    const void* src = d_in[3];
    const float* emb  = (const float*)d_in[8];
    const float* gcnW = (const float*)d_in[9];
    const float* wb   = (const float*)d_in[10];
    const float* gb   = (const float*)d_in[11];
    const float* p1W  = (const float*)d_in[12];
    const float* p1b  = (const float*)d_in[13];
    const float* p2W  = (const float*)d_in[14];
    const float* p2b  = (const float*)d_in[15];
    const float* lng  = (const float*)d_in[16];
    const float* lnb  = (const float*)d_in[17];
    const float* Wih  = (const float*)d_in[18];
    const float* Whh  = (const float*)d_in[19];
    const float* bih  = (const float*)d_in[20];
    const float* bhh  = (const float*)d_in[21];

    fp16 *p1h, *p2h, *Wihh, *Whhh, *xcath, *hench, *ench, *hh;
    float *xcat, *oenc, *sconst, *qWihb, *gates, *bsum;
    cudaGetSymbolAddress((void**)&p1h,   g_p1h);
    cudaGetSymbolAddress((void**)&p2h,   g_p2h);
    cudaGetSymbolAddress((void**)&Wihh,  g_Wihh);
    cudaGetSymbolAddress((void**)&Whhh,  g_Whhh);
    cudaGetSymbolAddress((void**)&xcath, g_xcath);
    cudaGetSymbolAddress((void**)&hench, g_hench);
    cudaGetSymbolAddress((void**)&ench,  g_ench);
    cudaGetSymbolAddress((void**)&hh,    g_hh);
    cudaGetSymbolAddress((void**)&xcat,  g_xcat);
    cudaGetSymbolAddress((void**)&oenc,  g_oenc);
    cudaGetSymbolAddress((void**)&sconst, g_sconst);
    cudaGetSymbolAddress((void**)&qWihb, g_qWihb);
    cudaGetSymbolAddress((void**)&gates, g_gates);
    cudaGetSymbolAddress((void**)&bsum,  g_bsum);

    prep_kernel<<<128, 256>>>(gcnW, wb, gb, bih, bhh, (const int*)qlc);
    cvt_emb_kernel<<<(NSYM * 16 + 255) / 256, 256>>>(emb, NSYM * 16);
    cvt_all_kernel<<<(T8_P1 + T8_P2 + T8_WI + T8_WH + 255) / 256, 256>>>(p1W, p2W, Wih, Whh);

    cudaFuncSetAttribute(proj_mma_kernel,
                         cudaFuncAttributeMaxDynamicSharedMemorySize, PROJ_SMEM);
    proj_mma_kernel<<<dim3(2, (NSYM + 127) / 128), 256, PROJ_SMEM>>>();

    neighbor_kernel<<<2 * BQ + 2 * FEW, 128>>>(qlc, qrc, slc, src);

    cudaFuncSetAttribute(hgemm1,
                         cudaFuncAttributeMaxDynamicSharedMemorySize, HG_SMEM);

    // henc = relu(xcat@p1W^T + p1b) -> fp16 only
    hgemm1<<<dim3(512 / 128, (NROWS + 127) / 128), 256, HG_SMEM>>>(
        NROWS, 512, 256, xcath, p1h, p1b, nullptr, nullptr, hench, 1);
    // oenc = henc@p2W^T + p2b + xcat
    hgemm1<<<dim3(256 / 128, (NROWS + 127) / 128), 256, HG_SMEM>>>(
        NROWS, 256, 512, hench, p2h, p2b, xcat, oenc, nullptr, 0);
    ln_kernel<<<NROWS, 256>>>(lng, lnb);

    mean_kernel<<<1, 256>>>();
    sconst_kernel<<<G4 * 32 / 256, 256>>>(Whh);

    // qWihb = enc@Wih^T + (b_ih + b_hh)
    hgemm1<<<dim3(G4 / 128, BQ / 128), 256, HG_SMEM>>>(
        BQ, G4, 256, ench, Wihh, bsum, nullptr, qWihb, nullptr, 0);

    lstm_kernel<<<(BQ * HID + 255) / 256, 256>>>(qWihb, 1);

    for (int s = 1; s < 4; ++s) {
        hgemm1<<<dim3(G4 / 128, BQ / 128), 256, HG_SMEM>>>(
            BQ, G4, 256, hh, Whhh, sconst, qWihb, gates, nullptr, 0);
        lstm_kernel<<<(BQ * HID + 255) / 256, 256>>>(gates, 0);
    }

    final_kernel<<<(BQ * 32 + 255) / 256, 256>>>((float*)d_out);
}

// round 10
// speedup vs baseline: 2.3383x; 1.0590x over previous
#include <cuda_runtime.h>
#include <cuda_fp16.h>
#include <cstdint>
#include <math.h>

// ---------------- problem constants ----------------
#define NSYM   200001
#define PADID  200000
#define BQ     1024
#define FEW    5
#define NB     200
#define DM     256
#define DI     512
#define HID    512
#define G4     2048
#define NROWS  (BQ + FEW)

typedef __half fp16;

// ---------------- device scratch ----------------
__device__ fp16  g_projh[(size_t)NSYM * 256];
__device__ fp16  g_Wph[256 * 128];
__device__ fp16  g_p1h[512 * 256];
__device__ fp16  g_p2h[256 * 512];
__device__ fp16  g_Wihh[2048 * 256];
__device__ fp16  g_Whhh[2048 * 256];
__device__ float g_biasproj[256];
__device__ float g_bsum[G4];
__device__ float g_xcat[NROWS * DM];
__device__ fp16  g_xcath[NROWS * DM];
__device__ fp16  g_hench[NROWS * DI];
__device__ float g_oenc[NROWS * DM];
__device__ float g_enc[NROWS * DM];
__device__ fp16  g_ench[NROWS * DM];
__device__ float g_support[DM];
__device__ float g_sconst[G4];
__device__ float g_qWihb[BQ * G4];
__device__ float g_gates[BQ * G4];
__device__ float g_h[BQ * DM];
__device__ fp16  g_hh[BQ * DM];
__device__ float g_c[BQ * HID];
__device__ int   g_is64;

// ---------------- helpers ----------------
__device__ __forceinline__ uint32_t smem_u32(const void* p) {
    uint32_t a;
    asm("{ .reg .u64 t; cvta.to.shared.u64 t, %1; cvt.u32.u64 %0, t; }" : "=r"(a) : "l"(p));
    return a;
}
__device__ __forceinline__ void ldmatrix4(uint32_t addr, uint32_t& r0, uint32_t& r1,
                                          uint32_t& r2, uint32_t& r3) {
    asm volatile("ldmatrix.sync.aligned.m8n8.x4.shared.b16 {%0,%1,%2,%3}, [%4];"
                 : "=r"(r0), "=r"(r1), "=r"(r2), "=r"(r3) : "r"(addr));
}
__device__ __forceinline__ void mma16816(float* d, const uint32_t* a,
                                         uint32_t b0, uint32_t b1) {
    asm volatile(
        "mma.sync.aligned.m16n8k16.row.col.f32.f16.f16.f32 "
        "{%0,%1,%2,%3}, {%4,%5,%6,%7}, {%8,%9}, {%0,%1,%2,%3};"
        : "+f"(d[0]), "+f"(d[1]), "+f"(d[2]), "+f"(d[3])
        : "r"(a[0]), "r"(a[1]), "r"(a[2]), "r"(a[3]), "r"(b0), "r"(b1));
}
__device__ __forceinline__ uint32_t pack_h2(fp16 a, fp16 b) {
    __half2 t(a, b);
    return *reinterpret_cast<uint32_t*>(&t);
}
__device__ __forceinline__ uint4 cvt8(const float* f) {
    return make_uint4(pack_h2(__float2half(f[0]), __float2half(f[1])),
                      pack_h2(__float2half(f[2]), __float2half(f[3])),
                      pack_h2(__float2half(f[4]), __float2half(f[5])),
                      pack_h2(__float2half(f[6]), __float2half(f[7])));
}

// ---------------- fused prep: detect + Wproj + biases + all weight cvt -----
#define T8_P1 (512 * 256 / 8)
#define T8_P2 (256 * 512 / 8)
#define T8_WI (2048 * 256 / 8)
#define T8_WH (2048 * 256 / 8)
#define T8_ALL (T8_P1 + T8_P2 + T8_WI + T8_WH)   // 163840

__global__ void prep_all_kernel(const float* __restrict__ gcnW,
                                const float* __restrict__ wb,
                                const float* __restrict__ gb,
                                const float* __restrict__ bih,
                                const float* __restrict__ bhh,
                                const int* __restrict__ qlc_i32,
                                const float* __restrict__ p1W,
                                const float* __restrict__ p2W,
                                const float* __restrict__ Wih,
                                const float* __restrict__ Whh) {
    int idx = blockIdx.x * blockDim.x + threadIdx.x;
    if (idx == 0) {
        int any = 0;
        for (int i = 1; i < 2 * NB; i += 2) any |= qlc_i32[i];
        g_is64 = (any == 0) ? 1 : 0;
    }
    if (idx < 256 * 128) {
        int j = idx >> 7, e = idx & 127;
        float v = (j < 128) ? gcnW[j * 256 + e] : gcnW[(j - 128) * 256 + 128 + e];
        g_Wph[idx] = __float2half(v);
    }
    if (idx < 256) g_biasproj[idx] = (idx < 128) ? (wb[idx] + gb[idx]) : 0.f;
    if (idx < G4)  g_bsum[idx] = bih[idx] + bhh[idx];

    // weight conversions (8 floats per thread)
    if (idx < T8_ALL) {
        const float* src;
        fp16* dst;
        int e0;
        if (idx < T8_P1) {
            e0 = idx * 8; src = p1W + e0; dst = g_p1h + e0;
        } else if (idx < T8_P1 + T8_P2) {
            e0 = (idx - T8_P1) * 8; src = p2W + e0; dst = g_p2h + e0;
        } else if (idx < T8_P1 + T8_P2 + T8_WI) {
            e0 = (idx - T8_P1 - T8_P2) * 8; src = Wih + e0; dst = g_Wihh + e0;
        } else {
            e0 = (idx - T8_P1 - T8_P2 - T8_WI) * 8;
            int row = e0 >> 8, col = e0 & 255;   // Whh: cols 0..255 of ldw=512
            src = Whh + (size_t)row * 512 + col;
            dst = g_Whhh + e0;
        }
        float4 v0 = *reinterpret_cast<const float4*>(src);
        float4 v1 = *reinterpret_cast<const float4*>(src + 4);
        float f[8] = {v0.x, v0.y, v0.z, v0.w, v1.x, v1.y, v1.z, v1.w};
        *reinterpret_cast<uint4*>(dst) = cvt8(f);
    }
}

// =====================================================================
// proj_mma v5: g_projh[NSYM,256] = fp16(emb @ Wproj^T + bias)
// - reads emb fp32 directly (fused conversion)
// - each CTA computes BOTH N-halves (A in smem reused)
// 256 threads (4Mx2N warps of 32x64), 104.4KB smem, 2 CTAs/SM.
// =====================================================================
#define ROWB 272
#define PA_OFF 0
#define PB_OFF (128 * ROWB)                    // B: 256 rows
#define PROJ_SMEM (PB_OFF + 256 * ROWB)        // 104448

__global__ void __launch_bounds__(256, 2)
proj_mma_kernel(const float* __restrict__ emb) {
    extern __shared__ char sm[];
    const uint32_t sbase = smem_u32(sm);
    const int tid = threadIdx.x;
    const int mbase = blockIdx.x * 128;

    // A tile: 128 rows x 128 fp32 -> fp16 (2048 chunks of 8 floats)
#pragma unroll
    for (int i = 0; i < 8; ++i) {
        int c = tid + i * 256;
        int row = c >> 4, ch = c & 15;
        int grow = mbase + row;
        uint4 h = make_uint4(0, 0, 0, 0);
        if (grow < NSYM) {
            const float* p = emb + (size_t)grow * 128 + ch * 8;
            float4 v0 = *reinterpret_cast<const float4*>(p);
            float4 v1 = *reinterpret_cast<const float4*>(p + 4);
            float f[8] = {v0.x, v0.y, v0.z, v0.w, v1.x, v1.y, v1.z, v1.w};
            h = cvt8(f);
        }
        *reinterpret_cast<uint4*>(sm + PA_OFF + row * ROWB + ch * 16) = h;
    }
    // B tile: all 256 rows x 128 fp16 (4096 chunks)
#pragma unroll
    for (int i = 0; i < 16; ++i) {
        int c = tid + i * 256;
        int row = c >> 4, ch = c & 15;
        uint4 h = *reinterpret_cast<const uint4*>(g_Wph + row * 128 + ch * 8);
        *reinterpret_cast<uint4*>(sm + PB_OFF + row * ROWB + ch * 16) = h;
    }
    __syncthreads();

    const int warp = tid >> 5, lane = tid & 31;
    const int wm = warp & 3, wn = warp >> 2;   // 4M x 2N (N covers 128 per half)
    const int m0 = wm * 32, n0 = wn * 64;

    const int a_row = (lane & 15);
    const int a_kadd = (lane >> 4) << 3;
    const int b_row = ((lane >> 4) << 3) + (lane & 7);
    const int b_kadd = ((lane >> 3) & 1) << 3;

    for (int half = 0; half < 2; ++half) {
        const uint32_t bofs = PB_OFF + half * 128 * ROWB;

        float acc[2][8][4];
#pragma unroll
        for (int i = 0; i < 2; ++i)
#pragma unroll
            for (int j = 0; j < 8; ++j)
#pragma unroll
                for (int q = 0; q < 4; ++q) acc[i][j][q] = 0.f;

#pragma unroll
        for (int ks = 0; ks < 8; ++ks) {
            const int k0 = ks * 16;
            uint32_t ra[2][4];
#pragma unroll
            for (int mi = 0; mi < 2; ++mi)
                ldmatrix4(sbase + PA_OFF + (m0 + mi * 16 + a_row) * ROWB + (k0 + a_kadd) * 2,
                          ra[mi][0], ra[mi][1], ra[mi][2], ra[mi][3]);
            uint32_t rb[4][4];
#pragma unroll
            for (int np = 0; np < 4; ++np)
                ldmatrix4(sbase + bofs + (n0 + np * 16 + b_row) * ROWB + (k0 + b_kadd) * 2,
                          rb[np][0], rb[np][1], rb[np][2], rb[np][3]);
#pragma unroll
            for (int mi = 0; mi < 2; ++mi)
#pragma unroll
                for (int ni = 0; ni < 8; ++ni)
                    mma16816(acc[mi][ni], ra[mi],
                             rb[ni >> 1][(ni & 1) * 2 + 0], rb[ni >> 1][(ni & 1) * 2 + 1]);
        }

        const int rbase = mbase + m0;
#pragma unroll
        for (int mi = 0; mi < 2; ++mi) {
#pragma unroll
            for (int ni = 0; ni < 8; ++ni) {
                int gcol = half * 128 + n0 + ni * 8 + (lane & 3) * 2;
                float b0 = g_biasproj[gcol], b1 = g_biasproj[gcol + 1];
                int r0 = rbase + mi * 16 + (lane >> 2);
                int r1 = r0 + 8;
                if (r0 < NSYM)
                    *reinterpret_cast<uint32_t*>(g_projh + (size_t)r0 * 256 + gcol) =
                        pack_h2(__float2half(acc[mi][ni][0] + b0),
                                __float2half(acc[mi][ni][1] + b1));
                if (r1 < NSYM)
                    *reinterpret_cast<uint32_t*>(g_projh + (size_t)r1 * 256 + gcol) =
                        pack_h2(__float2half(acc[mi][ni][2] + b0),
                                __float2half(acc[mi][ni][3] + b1));
            }
        }
    }
}

// =====================================================================
// plain fp16 HMMA GEMM: C[M,N] = A[M,K] @ B[N,K]^T (+bias,+add,relu)
// =====================================================================
#define KROWB 144
#define HG_A  0
#define HG_B  (128 * KROWB)
#define HG_SMEM (2 * 128 * KROWB)   // 36864

__global__ void __launch_bounds__(256, 2)
hgemm1(int M, int N, int K,
       const fp16* __restrict__ A, const fp16* __restrict__ B,
       const float* __restrict__ bias, const float* __restrict__ addMat,
       float* __restrict__ C, fp16* __restrict__ Chi, int doRelu) {
    extern __shared__ char sm[];
    const uint32_t sbase = smem_u32(sm);
    const int tid = threadIdx.x;
    const int mtile = blockIdx.y * 128, ntile = blockIdx.x * 128;

    const int warp = tid >> 5, lane = tid & 31;
    const int wm = warp & 3, wn = warp >> 2;
    const int m0 = wm * 32, n0 = wn * 64;

    float acc[2][8][4];
#pragma unroll
    for (int i = 0; i < 2; ++i)
#pragma unroll
        for (int j = 0; j < 8; ++j)
#pragma unroll
            for (int q = 0; q < 4; ++q) acc[i][j][q] = 0.f;

    const int a_row = (lane & 15);
    const int a_kadd = (lane >> 4) << 3;
    const int b_row = ((lane >> 4) << 3) + (lane & 7);
    const int b_kadd = ((lane >> 3) & 1) << 3;

    for (int kc = 0; kc < K; kc += 64) {
#pragma unroll
        for (int i = 0; i < 4; ++i) {
            int c = tid + i * 256;
            int row = c >> 3, ch = c & 7;
            int gk = kc + ch * 8;
            int grow = mtile + row;
            uint4 h = make_uint4(0, 0, 0, 0);
            if (grow < M)
                h = *reinterpret_cast<const uint4*>(A + (size_t)grow * K + gk);
            *reinterpret_cast<uint4*>(sm + HG_A + row * KROWB + ch * 16) = h;
        }
#pragma unroll
        for (int i = 0; i < 4; ++i) {
            int c = tid + i * 256;
            int row = c >> 3, ch = c & 7;
            int gk = kc + ch * 8;
            int grow = ntile + row;
            uint4 h = *reinterpret_cast<const uint4*>(B + (size_t)grow * K + gk);
            *reinterpret_cast<uint4*>(sm + HG_B + row * KROWB + ch * 16) = h;
        }
        __syncthreads();

#pragma unroll
        for (int ks = 0; ks < 4; ++ks) {
            const int k0 = ks * 16;
            uint32_t ra[2][4];
#pragma unroll
            for (int mi = 0; mi < 2; ++mi)
                ldmatrix4(sbase + HG_A + (m0 + mi * 16 + a_row) * KROWB + (k0 + a_kadd) * 2,
                          ra[mi][0], ra[mi][1], ra[mi][2], ra[mi][3]);
            uint32_t rb[4][4];
#pragma unroll
            for (int np = 0; np < 4; ++np)
                ldmatrix4(sbase + HG_B + (n0 + np * 16 + b_row) * KROWB + (k0 + b_kadd) * 2,
                          rb[np][0], rb[np][1], rb[np][2], rb[np][3]);
#pragma unroll
            for (int mi = 0; mi < 2; ++mi)
#pragma unroll
                for (int ni = 0; ni < 8; ++ni)
                    mma16816(acc[mi][ni], ra[mi],
                             rb[ni >> 1][(ni & 1) * 2 + 0], rb[ni >> 1][(ni & 1) * 2 + 1]);
        }
        __syncthreads();
    }

#pragma unroll
    for (int mi = 0; mi < 2; ++mi) {
#pragma unroll
        for (int ni = 0; ni < 8; ++ni) {
            int col = ntile + n0 + ni * 8 + (lane & 3) * 2;
            float b0 = bias ? bias[col] : 0.f;
            float b1 = bias ? bias[col + 1] : 0.f;
#pragma unroll
            for (int half = 0; half < 2; ++half) {
                int r = mtile + m0 + mi * 16 + (lane >> 2) + half * 8;
                if (r >= M) continue;
                float vx = acc[mi][ni][half * 2 + 0] + b0;
                float vy = acc[mi][ni][half * 2 + 1] + b1;
                if (addMat) {
                    vx += addMat[(size_t)r * N + col];
                    vy += addMat[(size_t)r * N + col + 1];
                }
                if (doRelu) { vx = fmaxf(vx, 0.f); vy = fmaxf(vy, 0.f); }
                if (C)
                    *reinterpret_cast<float2*>(C + (size_t)r * N + col) = make_float2(vx, vy);
                if (Chi)
                    *reinterpret_cast<uint32_t*>(Chi + (size_t)r * N + col) =
                        pack_h2(__float2half(vx), __float2half(vy));
            }
        }
    }
}

// ---------------- neighbor encoder (fp16 gather) ----------------
__global__ void __launch_bounds__(128)
neighbor_kernel(const void* qlc, const void* qrc, const void* slc, const void* src) {
    __shared__ int sidx[2 * NB];
    int b = blockIdx.x;
    const void* conn;
    int node, off;
    if (b < BQ)                { conn = qlc; node = b;                off = node * DM; }
    else if (b < 2 * BQ)       { conn = qrc; node = b - BQ;           off = node * DM + 128; }
    else if (b < 2 * BQ + FEW) { conn = slc; node = b - 2 * BQ;       off = (BQ + node) * DM; }
    else                       { conn = src; node = b - 2 * BQ - FEW; off = (BQ + node) * DM + 128; }

    int tid = threadIdx.x;
    size_t base = (size_t)node * (2 * NB);
    if (g_is64) {
        const long long* p = (const long long*)conn;
        for (int t = tid; t < 2 * NB; t += 128) sidx[t] = (int)p[base + t];
    } else {
        const int* p = (const int*)conn;
        for (int t = tid; t < 2 * NB; t += 128) sidx[t] = p[base + t];
    }
    __syncthreads();

    const fp16* __restrict__ proj = g_projh;
    float m = -INFINITY;
#pragma unroll 2
    for (int k = 0; k < NB; ++k) {
        int rel = sidx[2 * k], ent = sidx[2 * k + 1];
        if (rel == PADID || ent == PADID) continue;
        float v = __half2float(proj[(size_t)rel * 256 + tid]) +
                  __half2float(proj[(size_t)ent * 256 + 128 + tid]);
        v = (v > 0.f) ? v : 0.1f * v;
        m = fmaxf(m, v);
    }
    float t = tanhf(m);
    g_xcat[off + tid] = t;
    g_xcath[off + tid] = __float2half(t);
}

// ---------------- layernorm ----------------
__global__ void ln_kernel(const float* __restrict__ lg, const float* __restrict__ lb) {
    __shared__ float red[256];
    int row = blockIdx.x, t = threadIdx.x;
    float v = g_oenc[row * DM + t];
    red[t] = v;
    __syncthreads();
    for (int s = 128; s > 0; s >>= 1) { if (t < s) red[t] += red[t + s]; __syncthreads(); }
    float mu = red[0] * (1.f / 256.f);
    __syncthreads();
    float d = v - mu;
    red[t] = d * d;
    __syncthreads();
    for (int s = 128; s > 0; s >>= 1) { if (t < s) red[t] += red[t + s]; __syncthreads(); }
    float var = red[0] * (1.f / 256.f);
    float o = d * rsqrtf(var + 1e-5f) * lg[t] + lb[t];
    g_enc[row * DM + t] = o;
    g_ench[row * DM + t] = __float2half(o);
}

// ---------------- fused mean + sconst (64 blocks x 256 thr) ----------------
__global__ void sconst2_kernel(const float* __restrict__ Whh) {
    __shared__ float sup[256];
    int t = threadIdx.x;
    float s = 0.f;
    for (int r = 0; r < FEW; ++r) s += g_enc[(BQ + r) * DM + t];
    s *= (1.f / FEW);
    sup[t] = s;
    if (blockIdx.x == 0) g_support[t] = s;
    __syncthreads();

    int warp = t >> 5, lane = t & 31;
#pragma unroll
    for (int gi = 0; gi < 4; ++gi) {
        int gidx = blockIdx.x * 32 + warp * 4 + gi;
        float acc = 0.f;
        for (int i = lane; i < DM; i += 32)
            acc += sup[i] * Whh[(size_t)gidx * 512 + 256 + i];
#pragma unroll
        for (int o = 16; o > 0; o >>= 1) acc += __shfl_down_sync(0xffffffffu, acc, o);
        if (lane == 0) g_sconst[gidx] = acc;
    }
}

// ---------------- LSTM elementwise step (steps 1..3) ----------------
__device__ __forceinline__ float sigm(float x) { return 1.f / (1.f + expf(-x)); }

__global__ void lstm_kernel(const float* __restrict__ G, int firstStep) {
    int idx = blockIdx.x * blockDim.x + threadIdx.x;
    if (idx >= BQ * HID) return;
    int n = idx >> 9, j = idx & 511;
    const float* g = G + (size_t)n * G4;
    float gi = g[j], gf = g[512 + j], gg = g[1024 + j], go = g[1536 + j];
    float c  = firstStep ? 0.f : g_c[idx];
    float cn = sigm(gf) * c + sigm(gi) * tanhf(gg);
    g_c[idx] = cn;
    if (j < DM) {
        float hv = g_enc[n * DM + j] + sigm(go) * tanhf(cn);
        g_h[n * DM + j] = hv;
        g_hh[n * DM + j] = __float2half(hv);
    }
}

// ---------------- last LSTM step fused with final dot ----------------
__global__ void lstm_last_kernel(const float* __restrict__ G, float* __restrict__ out) {
    __shared__ float red[256];
    int n = blockIdx.x, j = threadIdx.x;   // j in [0,256)
    const float* g = G + (size_t)n * G4;
    float gi = g[j], gf = g[512 + j], gg = g[1024 + j], go = g[1536 + j];
    float c  = g_c[n * 512 + j];
    float cn = sigm(gf) * c + sigm(gi) * tanhf(gg);
    float hv = g_enc[n * DM + j] + sigm(go) * tanhf(cn);
    red[j] = hv * g_support[j];
    __syncthreads();
    for (int s = 128; s > 0; s >>= 1) { if (j < s) red[j] += red[j + s]; __syncthreads(); }
    if (j == 0) out[n] = red[0];
}

// ---------------- launch ----------------
extern "C" void kernel_launch(void* const* d_in, const int* in_sizes, int n_in,
                              void* d_out, int out_size) {
    const void* qlc = d_in[0];
    const void* qrc = d_in[1];
    const void* slc = d_in[2];
    const void* src = d_in[3];
    const float* emb  = (const float*)d_in[8];
    const float* gcnW = (const float*)d_in[9];
    const float* wb   = (const float*)d_in[10];
    const float* gb   = (const float*)d_in[11];
    const float* p1W  = (const float*)d_in[12];
    const float* p1b  = (const float*)d_in[13];
    const float* p2W  = (const float*)d_in[14];
    const float* p2b  = (const float*)d_in[15];
    const float* lng  = (const float*)d_in[16];
    const float* lnb  = (const float*)d_in[17];
    const float* Wih  = (const float*)d_in[18];
    const float* Whh  = (const float*)d_in[19];
    const float* bih  = (const float*)d_in[20];
    const float* bhh  = (const float*)d_in[21];

    fp16 *p1h, *p2h, *Wihh, *Whhh, *xcath, *hench, *ench, *hh;
    float *xcat, *oenc, *sconst, *qWihb, *gates, *bsum;
    cudaGetSymbolAddress((void**)&p1h,    g_p1h);
    cudaGetSymbolAddress((void**)&p2h,    g_p2h);
    cudaGetSymbolAddress((void**)&Wihh,   g_Wihh);
    cudaGetSymbolAddress((void**)&Whhh,   g_Whhh);
    cudaGetSymbolAddress((void**)&xcath,  g_xcath);
    cudaGetSymbolAddress((void**)&hench,  g_hench);
    cudaGetSymbolAddress((void**)&ench,   g_ench);
    cudaGetSymbolAddress((void**)&hh,     g_hh);
    cudaGetSymbolAddress((void**)&xcat,   g_xcat);
    cudaGetSymbolAddress((void**)&oenc,   g_oenc);
    cudaGetSymbolAddress((void**)&sconst, g_sconst);
    cudaGetSymbolAddress((void**)&qWihb,  g_qWihb);
    cudaGetSymbolAddress((void**)&gates,  g_gates);
    cudaGetSymbolAddress((void**)&bsum,   g_bsum);

    prep_all_kernel<<<(T8_ALL + 255) / 256, 256>>>(
        gcnW, wb, gb, bih, bhh, (const int*)qlc, p1W, p2W, Wih, Whh);

    cudaFuncSetAttribute(proj_mma_kernel,
                         cudaFuncAttributeMaxDynamicSharedMemorySize, PROJ_SMEM);
    proj_mma_kernel<<<(NSYM + 127) / 128, 256, PROJ_SMEM>>>(emb);

    neighbor_kernel<<<2 * BQ + 2 * FEW, 128>>>(qlc, qrc, slc, src);

    cudaFuncSetAttribute(hgemm1,
                         cudaFuncAttributeMaxDynamicSharedMemorySize, HG_SMEM);

    // henc = relu(xcat@p1W^T + p1b) -> fp16 only
    hgemm1<<<dim3(512 / 128, (NROWS + 127) / 128), 256, HG_SMEM>>>(
        NROWS, 512, 256, xcath, p1h, p1b, nullptr, nullptr, hench, 1);
    // oenc = henc@p2W^T + p2b + xcat
    hgemm1<<<dim3(256 / 128, (NROWS + 127) / 128), 256, HG_SMEM>>>(
        NROWS, 256, 512, hench, p2h, p2b, xcat, oenc, nullptr, 0);
    ln_kernel<<<NROWS, 256>>>(lng, lnb);

    sconst2_kernel<<<G4 / 32, 256>>>(Whh);

    // qWihb = enc@Wih^T + (b_ih + b_hh)
    hgemm1<<<dim3(G4 / 128, BQ / 128), 256, HG_SMEM>>>(
        BQ, G4, 256, ench, Wihh, bsum, nullptr, qWihb, nullptr, 0);

    // step 1
    lstm_kernel<<<(BQ * HID + 255) / 256, 256>>>(qWihb, 1);

    // steps 2..3 (full), step 4 gates + fused last
    for (int s = 1; s < 3; ++s) {
        hgemm1<<<dim3(G4 / 128, BQ / 128), 256, HG_SMEM>>>(
            BQ, G4, 256, hh, Whhh, sconst, qWihb, gates, nullptr, 0);
        lstm_kernel<<<(BQ * HID + 255) / 256, 256>>>(gates, 0);
    }
    hgemm1<<<dim3(G4 / 128, BQ / 128), 256, HG_SMEM>>>(
        BQ, G4, 256, hh, Whhh, sconst, qWihb, gates, nullptr, 0);
    lstm_last_kernel<<<BQ, 256>>>(gates, (float*)d_out);
}

// round 11
// speedup vs baseline: 2.6537x; 1.1349x over previous
#include <cuda_runtime.h>
#include <cuda_fp16.h>
#include <cstdint>
#include <math.h>

// ---------------- problem constants ----------------
#define NSYM   200001
#define PADID  200000
#define BQ     1024
#define FEW    5
#define NB     200
#define DM     256
#define DI     512
#define HID    512
#define G4     2048
#define NROWS  (BQ + FEW)

typedef __half fp16;

// ---------------- device scratch ----------------
__device__ fp16  g_projh[(size_t)NSYM * 256];
__device__ fp16  g_Wph[256 * 128];
__device__ fp16  g_p1h[512 * 256];
__device__ fp16  g_p2h[256 * 512];
__device__ fp16  g_Wihh[2048 * 256];
__device__ fp16  g_Whhh[2048 * 256];
__device__ float g_biasproj[256];
__device__ float g_bsum[G4];
__device__ float g_xcat[NROWS * DM];
__device__ fp16  g_xcath[NROWS * DM];
__device__ fp16  g_hench[NROWS * DI];
__device__ float g_oenc[NROWS * DM];
__device__ float g_enc[NROWS * DM];
__device__ fp16  g_ench[NROWS * DM];
__device__ float g_support[DM];
__device__ float g_sconst[G4];
__device__ float g_qWihb[BQ * G4];
__device__ float g_gates[BQ * G4];
__device__ float g_h[BQ * DM];
__device__ fp16  g_hh[BQ * DM];
__device__ float g_c[BQ * HID];
__device__ int   g_is64;

// ---------------- helpers ----------------
__device__ __forceinline__ uint32_t smem_u32(const void* p) {
    uint32_t a;
    asm("{ .reg .u64 t; cvta.to.shared.u64 t, %1; cvt.u32.u64 %0, t; }" : "=r"(a) : "l"(p));
    return a;
}
__device__ __forceinline__ void ldmatrix4(uint32_t addr, uint32_t& r0, uint32_t& r1,
                                          uint32_t& r2, uint32_t& r3) {
    asm volatile("ldmatrix.sync.aligned.m8n8.x4.shared.b16 {%0,%1,%2,%3}, [%4];"
                 : "=r"(r0), "=r"(r1), "=r"(r2), "=r"(r3) : "r"(addr));
}
__device__ __forceinline__ void mma16816(float* d, const uint32_t* a,
                                         uint32_t b0, uint32_t b1) {
    asm volatile(
        "mma.sync.aligned.m16n8k16.row.col.f32.f16.f16.f32 "
        "{%0,%1,%2,%3}, {%4,%5,%6,%7}, {%8,%9}, {%0,%1,%2,%3};"
        : "+f"(d[0]), "+f"(d[1]), "+f"(d[2]), "+f"(d[3])
        : "r"(a[0]), "r"(a[1]), "r"(a[2]), "r"(a[3]), "r"(b0), "r"(b1));
}
__device__ __forceinline__ uint32_t pack_h2(fp16 a, fp16 b) {
    __half2 t(a, b);
    return *reinterpret_cast<uint32_t*>(&t);
}
__device__ __forceinline__ uint4 cvt8(const float* f) {
    return make_uint4(pack_h2(__float2half(f[0]), __float2half(f[1])),
                      pack_h2(__float2half(f[2]), __float2half(f[3])),
                      pack_h2(__float2half(f[4]), __float2half(f[5])),
                      pack_h2(__float2half(f[6]), __float2half(f[7])));
}

// ---------------- fused prep ----------------
#define T8_P1 (512 * 256 / 8)
#define T8_P2 (256 * 512 / 8)
#define T8_WI (2048 * 256 / 8)
#define T8_WH (2048 * 256 / 8)
#define T8_ALL (T8_P1 + T8_P2 + T8_WI + T8_WH)

__global__ void prep_all_kernel(const float* __restrict__ gcnW,
                                const float* __restrict__ wb,
                                const float* __restrict__ gb,
                                const float* __restrict__ bih,
                                const float* __restrict__ bhh,
                                const int* __restrict__ qlc_i32,
                                const float* __restrict__ p1W,
                                const float* __restrict__ p2W,
                                const float* __restrict__ Wih,
                                const float* __restrict__ Whh) {
    int idx = blockIdx.x * blockDim.x + threadIdx.x;
    if (idx == 0) {
        int any = 0;
        for (int i = 1; i < 2 * NB; i += 2) any |= qlc_i32[i];
        g_is64 = (any == 0) ? 1 : 0;
    }
    if (idx < 256 * 128) {
        int j = idx >> 7, e = idx & 127;
        float v = (j < 128) ? gcnW[j * 256 + e] : gcnW[(j - 128) * 256 + 128 + e];
        g_Wph[idx] = __float2half(v);
    }
    if (idx < 256) g_biasproj[idx] = (idx < 128) ? (wb[idx] + gb[idx]) : 0.f;
    if (idx < G4)  g_bsum[idx] = bih[idx] + bhh[idx];

    if (idx < T8_ALL) {
        const float* src;
        fp16* dst;
        int e0;
        if (idx < T8_P1) {
            e0 = idx * 8; src = p1W + e0; dst = g_p1h + e0;
        } else if (idx < T8_P1 + T8_P2) {
            e0 = (idx - T8_P1) * 8; src = p2W + e0; dst = g_p2h + e0;
        } else if (idx < T8_P1 + T8_P2 + T8_WI) {
            e0 = (idx - T8_P1 - T8_P2) * 8; src = Wih + e0; dst = g_Wihh + e0;
        } else {
            e0 = (idx - T8_P1 - T8_P2 - T8_WI) * 8;
            int row = e0 >> 8, col = e0 & 255;
            src = Whh + (size_t)row * 512 + col;
            dst = g_Whhh + e0;
        }
        float4 v0 = *reinterpret_cast<const float4*>(src);
        float4 v1 = *reinterpret_cast<const float4*>(src + 4);
        float f[8] = {v0.x, v0.y, v0.z, v0.w, v1.x, v1.y, v1.z, v1.w};
        *reinterpret_cast<uint4*>(dst) = cvt8(f);
    }
}

// =====================================================================
// proj_mma: g_projh[NSYM,256] = fp16(emb @ Wproj^T + bias)
// =====================================================================
#define ROWB 272
#define PA_OFF 0
#define PB_OFF (128 * ROWB)
#define PROJ_SMEM (PB_OFF + 256 * ROWB)   // 104448

__global__ void __launch_bounds__(256, 2)
proj_mma_kernel(const float* __restrict__ emb) {
    extern __shared__ char sm[];
    const uint32_t sbase = smem_u32(sm);
    const int tid = threadIdx.x;
    const int mbase = blockIdx.x * 128;

#pragma unroll
    for (int i = 0; i < 8; ++i) {
        int c = tid + i * 256;
        int row = c >> 4, ch = c & 15;
        int grow = mbase + row;
        uint4 h = make_uint4(0, 0, 0, 0);
        if (grow < NSYM) {
            const float* p = emb + (size_t)grow * 128 + ch * 8;
            float4 v0 = *reinterpret_cast<const float4*>(p);
            float4 v1 = *reinterpret_cast<const float4*>(p + 4);
            float f[8] = {v0.x, v0.y, v0.z, v0.w, v1.x, v1.y, v1.z, v1.w};
            h = cvt8(f);
        }
        *reinterpret_cast<uint4*>(sm + PA_OFF + row * ROWB + ch * 16) = h;
    }
#pragma unroll
    for (int i = 0; i < 16; ++i) {
        int c = tid + i * 256;
        int row = c >> 4, ch = c & 15;
        uint4 h = *reinterpret_cast<const uint4*>(g_Wph + row * 128 + ch * 8);
        *reinterpret_cast<uint4*>(sm + PB_OFF + row * ROWB + ch * 16) = h;
    }
    __syncthreads();

    const int warp = tid >> 5, lane = tid & 31;
    const int wm = warp & 3, wn = warp >> 2;
    const int m0 = wm * 32, n0 = wn * 64;

    const int a_row = (lane & 15);
    const int a_kadd = (lane >> 4) << 3;
    const int b_row = ((lane >> 4) << 3) + (lane & 7);
    const int b_kadd = ((lane >> 3) & 1) << 3;

    for (int half = 0; half < 2; ++half) {
        const uint32_t bofs = PB_OFF + half * 128 * ROWB;

        float acc[2][8][4];
#pragma unroll
        for (int i = 0; i < 2; ++i)
#pragma unroll
            for (int j = 0; j < 8; ++j)
#pragma unroll
                for (int q = 0; q < 4; ++q) acc[i][j][q] = 0.f;

#pragma unroll
        for (int ks = 0; ks < 8; ++ks) {
            const int k0 = ks * 16;
            uint32_t ra[2][4];
#pragma unroll
            for (int mi = 0; mi < 2; ++mi)
                ldmatrix4(sbase + PA_OFF + (m0 + mi * 16 + a_row) * ROWB + (k0 + a_kadd) * 2,
                          ra[mi][0], ra[mi][1], ra[mi][2], ra[mi][3]);
            uint32_t rb[4][4];
#pragma unroll
            for (int np = 0; np < 4; ++np)
                ldmatrix4(sbase + bofs + (n0 + np * 16 + b_row) * ROWB + (k0 + b_kadd) * 2,
                          rb[np][0], rb[np][1], rb[np][2], rb[np][3]);
#pragma unroll
            for (int mi = 0; mi < 2; ++mi)
#pragma unroll
                for (int ni = 0; ni < 8; ++ni)
                    mma16816(acc[mi][ni], ra[mi],
                             rb[ni >> 1][(ni & 1) * 2 + 0], rb[ni >> 1][(ni & 1) * 2 + 1]);
        }

        const int rbase = mbase + m0;
#pragma unroll
        for (int mi = 0; mi < 2; ++mi) {
#pragma unroll
            for (int ni = 0; ni < 8; ++ni) {
                int gcol = half * 128 + n0 + ni * 8 + (lane & 3) * 2;
                float b0 = g_biasproj[gcol], b1 = g_biasproj[gcol + 1];
                int r0 = rbase + mi * 16 + (lane >> 2);
                int r1 = r0 + 8;
                if (r0 < NSYM)
                    *reinterpret_cast<uint32_t*>(g_projh + (size_t)r0 * 256 + gcol) =
                        pack_h2(__float2half(acc[mi][ni][0] + b0),
                                __float2half(acc[mi][ni][1] + b1));
                if (r1 < NSYM)
                    *reinterpret_cast<uint32_t*>(g_projh + (size_t)r1 * 256 + gcol) =
                        pack_h2(__float2half(acc[mi][ni][2] + b0),
                                __float2half(acc[mi][ni][3] + b1));
            }
        }
    }
}

// =====================================================================
// hgemm_small: 64(M) x 128(N) tile, 128 threads (2Mx2N warps of 32x64)
// 4 CTAs/SM. Used for all small GEMMs.
// =====================================================================
#define KROWB 144
#define HS_A  0
#define HS_B  (64 * KROWB)
#define HS_SMEM ((64 + 128) * KROWB)   // 27648

__global__ void __launch_bounds__(128, 4)
hgemm_small(int M, int N, int K,
            const fp16* __restrict__ A, const fp16* __restrict__ B,
            const float* __restrict__ bias, const float* __restrict__ addMat,
            float* __restrict__ C, fp16* __restrict__ Chi, int doRelu) {
    extern __shared__ char sm[];
    const uint32_t sbase = smem_u32(sm);
    const int tid = threadIdx.x;
    const int mtile = blockIdx.y * 64, ntile = blockIdx.x * 128;

    const int warp = tid >> 5, lane = tid & 31;
    const int wm = warp & 1, wn = warp >> 1;
    const int m0 = wm * 32, n0 = wn * 64;

    float acc[2][8][4];
#pragma unroll
    for (int i = 0; i < 2; ++i)
#pragma unroll
        for (int j = 0; j < 8; ++j)
#pragma unroll
            for (int q = 0; q < 4; ++q) acc[i][j][q] = 0.f;

    const int a_row = (lane & 15);
    const int a_kadd = (lane >> 4) << 3;
    const int b_row = ((lane >> 4) << 3) + (lane & 7);
    const int b_kadd = ((lane >> 3) & 1) << 3;

    for (int kc = 0; kc < K; kc += 64) {
        // A: 64 rows x 64 fp16 = 512 chunks of 8
#pragma unroll
        for (int i = 0; i < 4; ++i) {
            int c = tid + i * 128;
            int row = c >> 3, ch = c & 7;
            int grow = mtile + row;
            uint4 h = make_uint4(0, 0, 0, 0);
            if (grow < M)
                h = *reinterpret_cast<const uint4*>(A + (size_t)grow * K + kc + ch * 8);
            *reinterpret_cast<uint4*>(sm + HS_A + row * KROWB + ch * 16) = h;
        }
        // B: 128 rows x 64 = 1024 chunks
#pragma unroll
        for (int i = 0; i < 8; ++i) {
            int c = tid + i * 128;
            int row = c >> 3, ch = c & 7;
            int grow = ntile + row;
            uint4 h = *reinterpret_cast<const uint4*>(B + (size_t)grow * K + kc + ch * 8);
            *reinterpret_cast<uint4*>(sm + HS_B + row * KROWB + ch * 16) = h;
        }
        __syncthreads();

#pragma unroll
        for (int ks = 0; ks < 4; ++ks) {
            const int k0 = ks * 16;
            uint32_t ra[2][4];
#pragma unroll
            for (int mi = 0; mi < 2; ++mi)
                ldmatrix4(sbase + HS_A + (m0 + mi * 16 + a_row) * KROWB + (k0 + a_kadd) * 2,
                          ra[mi][0], ra[mi][1], ra[mi][2], ra[mi][3]);
            uint32_t rb[4][4];
#pragma unroll
            for (int np = 0; np < 4; ++np)
                ldmatrix4(sbase + HS_B + (n0 + np * 16 + b_row) * KROWB + (k0 + b_kadd) * 2,
                          rb[np][0], rb[np][1], rb[np][2], rb[np][3]);
#pragma unroll
            for (int mi = 0; mi < 2; ++mi)
#pragma unroll
                for (int ni = 0; ni < 8; ++ni)
                    mma16816(acc[mi][ni], ra[mi],
                             rb[ni >> 1][(ni & 1) * 2 + 0], rb[ni >> 1][(ni & 1) * 2 + 1]);
        }
        __syncthreads();
    }

#pragma unroll
    for (int mi = 0; mi < 2; ++mi) {
#pragma unroll
        for (int ni = 0; ni < 8; ++ni) {
            int col = ntile + n0 + ni * 8 + (lane & 3) * 2;
            float b0 = bias ? bias[col] : 0.f;
            float b1 = bias ? bias[col + 1] : 0.f;
#pragma unroll
            for (int half = 0; half < 2; ++half) {
                int r = mtile + m0 + mi * 16 + (lane >> 2) + half * 8;
                if (r >= M) continue;
                float vx = acc[mi][ni][half * 2 + 0] + b0;
                float vy = acc[mi][ni][half * 2 + 1] + b1;
                if (addMat) {
                    vx += addMat[(size_t)r * N + col];
                    vy += addMat[(size_t)r * N + col + 1];
                }
                if (doRelu) { vx = fmaxf(vx, 0.f); vy = fmaxf(vy, 0.f); }
                if (C)
                    *reinterpret_cast<float2*>(C + (size_t)r * N + col) = make_float2(vx, vy);
                if (Chi)
                    *reinterpret_cast<uint32_t*>(Chi + (size_t)r * N + col) =
                        pack_h2(__float2half(vx), __float2half(vy));
            }
        }
    }
}

// ---------------- neighbor encoder v2: half2 full-line gather, split-k ----
__global__ void __launch_bounds__(128)
neighbor_kernel(const void* qlc, const void* qrc, const void* slc, const void* src) {
    __shared__ int sidx[2 * NB];
    __shared__ float redA[128];   // even-parity partial maxima (2 per col-pair thread)
    int b = blockIdx.x;
    const void* conn;
    int node, off;
    if (b < BQ)                { conn = qlc; node = b;                off = node * DM; }
    else if (b < 2 * BQ)       { conn = qrc; node = b - BQ;           off = node * DM + 128; }
    else if (b < 2 * BQ + FEW) { conn = slc; node = b - 2 * BQ;       off = (BQ + node) * DM; }
    else                       { conn = src; node = b - 2 * BQ - FEW; off = (BQ + node) * DM + 128; }

    int tid = threadIdx.x;
    size_t base = (size_t)node * (2 * NB);
    if (g_is64) {
        const long long* p = (const long long*)conn;
        for (int t = tid; t < 2 * NB; t += 128) sidx[t] = (int)p[base + t];
    } else {
        const int* p = (const int*)conn;
        for (int t = tid; t < 2 * NB; t += 128) sidx[t] = p[base + t];
    }
    __syncthreads();

    const fp16* __restrict__ proj = g_projh;
    const int grp = tid >> 6;          // 0: even k, 1: odd k
    const int c2 = (tid & 63) * 2;     // column pair

    float m0 = -INFINITY, m1 = -INFINITY;
    for (int k = grp; k < NB; k += 2) {
        int rel = sidx[2 * k], ent = sidx[2 * k + 1];
        if (rel == PADID || ent == PADID) continue;
        __half2 a = *reinterpret_cast<const __half2*>(proj + (size_t)rel * 256 + c2);
        __half2 e = *reinterpret_cast<const __half2*>(proj + (size_t)ent * 256 + 128 + c2);
        float v0 = __half2float(__low2half(a)) + __half2float(__low2half(e));
        float v1 = __half2float(__high2half(a)) + __half2float(__high2half(e));
        v0 = (v0 > 0.f) ? v0 : 0.1f * v0;
        v1 = (v1 > 0.f) ? v1 : 0.1f * v1;
        m0 = fmaxf(m0, v0);
        m1 = fmaxf(m1, v1);
    }

    if (grp == 0) { redA[c2] = m0; redA[c2 + 1] = m1; }
    __syncthreads();
    if (grp == 1) {
        float f0 = tanhf(fmaxf(m0, redA[c2]));
        float f1 = tanhf(fmaxf(m1, redA[c2 + 1]));
        *reinterpret_cast<float2*>(g_xcat + off + c2) = make_float2(f0, f1);
        *reinterpret_cast<uint32_t*>(g_xcath + off + c2) =
            pack_h2(__float2half(f0), __float2half(f1));
    }
}

// ---------------- layernorm ----------------
__global__ void ln_kernel(const float* __restrict__ lg, const float* __restrict__ lb) {
    __shared__ float red[256];
    int row = blockIdx.x, t = threadIdx.x;
    float v = g_oenc[row * DM + t];
    red[t] = v;
    __syncthreads();
    for (int s = 128; s > 0; s >>= 1) { if (t < s) red[t] += red[t + s]; __syncthreads(); }
    float mu = red[0] * (1.f / 256.f);
    __syncthreads();
    float d = v - mu;
    red[t] = d * d;
    __syncthreads();
    for (int s = 128; s > 0; s >>= 1) { if (t < s) red[t] += red[t + s]; __syncthreads(); }
    float var = red[0] * (1.f / 256.f);
    float o = d * rsqrtf(var + 1e-5f) * lg[t] + lb[t];
    g_enc[row * DM + t] = o;
    g_ench[row * DM + t] = __float2half(o);
}

// ---------------- fused mean + sconst ----------------
__global__ void sconst2_kernel(const float* __restrict__ Whh) {
    __shared__ float sup[256];
    int t = threadIdx.x;
    float s = 0.f;
    for (int r = 0; r < FEW; ++r) s += g_enc[(BQ + r) * DM + t];
    s *= (1.f / FEW);
    sup[t] = s;
    if (blockIdx.x == 0) g_support[t] = s;
    __syncthreads();

    int warp = t >> 5, lane = t & 31;
#pragma unroll
    for (int gi = 0; gi < 4; ++gi) {
        int gidx = blockIdx.x * 32 + warp * 4 + gi;
        float acc = 0.f;
        for (int i = lane; i < DM; i += 32)
            acc += sup[i] * Whh[(size_t)gidx * 512 + 256 + i];
#pragma unroll
        for (int o = 16; o > 0; o >>= 1) acc += __shfl_down_sync(0xffffffffu, acc, o);
        if (lane == 0) g_sconst[gidx] = acc;
    }
}

// ---------------- LSTM elementwise step ----------------
__device__ __forceinline__ float sigm(float x) { return 1.f / (1.f + expf(-x)); }

__global__ void lstm_kernel(const float* __restrict__ G, int firstStep) {
    int idx = blockIdx.x * blockDim.x + threadIdx.x;
    if (idx >= BQ * HID) return;
    int n = idx >> 9, j = idx & 511;
    const float* g = G + (size_t)n * G4;
    float gi = g[j], gf = g[512 + j], gg = g[1024 + j], go = g[1536 + j];
    float c  = firstStep ? 0.f : g_c[idx];
    float cn = sigm(gf) * c + sigm(gi) * tanhf(gg);
    g_c[idx] = cn;
    if (j < DM) {
        float hv = g_enc[n * DM + j] + sigm(go) * tanhf(cn);
        g_h[n * DM + j] = hv;
        g_hh[n * DM + j] = __float2half(hv);
    }
}

// ---------------- last LSTM step fused with final dot ----------------
__global__ void lstm_last_kernel(const float* __restrict__ G, float* __restrict__ out) {
    __shared__ float red[256];
    int n = blockIdx.x, j = threadIdx.x;
    const float* g = G + (size_t)n * G4;
    float gi = g[j], gf = g[512 + j], gg = g[1024 + j], go = g[1536 + j];
    float c  = g_c[n * 512 + j];
    float cn = sigm(gf) * c + sigm(gi) * tanhf(gg);
    float hv = g_enc[n * DM + j] + sigm(go) * tanhf(cn);
    red[j] = hv * g_support[j];
    __syncthreads();
    for (int s = 128; s > 0; s >>= 1) { if (j < s) red[j] += red[j + s]; __syncthreads(); }
    if (j == 0) out[n] = red[0];
}

// ---------------- launch ----------------
extern "C" void kernel_launch(void* const* d_in, const int* in_sizes, int n_in,
                              void* d_out, int out_size) {
    const void* qlc = d_in[0];
    const void* qrc = d_in[1];
    const void* slc = d_in[2];
    const void* src = d_in[3];
    const float* emb  = (const float*)d_in[8];
    const float* gcnW = (const float*)d_in[9];
    const float* wb   = (const float*)d_in[10];
    const float* gb   = (const float*)d_in[11];
    const float* p1W  = (const float*)d_in[12];
    const float* p1b  = (const float*)d_in[13];
    const float* p2W  = (const float*)d_in[14];
    const float* p2b  = (const float*)d_in[15];
    const float* lng  = (const float*)d_in[16];
    const float* lnb  = (const float*)d_in[17];
    const float* Wih  = (const float*)d_in[18];
    const float* Whh  = (const float*)d_in[19];
    const float* bih  = (const float*)d_in[20];
    const float* bhh  = (const float*)d_in[21];

    fp16 *p1h, *p2h, *Wihh, *Whhh, *xcath, *hench, *ench, *hh;
    float *xcat, *oenc, *sconst, *qWihb, *gates, *bsum;
    cudaGetSymbolAddress((void**)&p1h,    g_p1h);
    cudaGetSymbolAddress((void**)&p2h,    g_p2h);
    cudaGetSymbolAddress((void**)&Wihh,   g_Wihh);
    cudaGetSymbolAddress((void**)&Whhh,   g_Whhh);
    cudaGetSymbolAddress((void**)&xcath,  g_xcath);
    cudaGetSymbolAddress((void**)&hench,  g_hench);
    cudaGetSymbolAddress((void**)&ench,   g_ench);
    cudaGetSymbolAddress((void**)&hh,     g_hh);
    cudaGetSymbolAddress((void**)&xcat,   g_xcat);
    cudaGetSymbolAddress((void**)&oenc,   g_oenc);
    cudaGetSymbolAddress((void**)&sconst, g_sconst);
    cudaGetSymbolAddress((void**)&qWihb,  g_qWihb);
    cudaGetSymbolAddress((void**)&gates,  g_gates);
    cudaGetSymbolAddress((void**)&bsum,   g_bsum);

    prep_all_kernel<<<(T8_ALL + 255) / 256, 256>>>(
        gcnW, wb, gb, bih, bhh, (const int*)qlc, p1W, p2W, Wih, Whh);

    cudaFuncSetAttribute(proj_mma_kernel,
                         cudaFuncAttributeMaxDynamicSharedMemorySize, PROJ_SMEM);
    proj_mma_kernel<<<(NSYM + 127) / 128, 256, PROJ_SMEM>>>(emb);

    neighbor_kernel<<<2 * BQ + 2 * FEW, 128>>>(qlc, qrc, slc, src);

    cudaFuncSetAttribute(hgemm_small,
                         cudaFuncAttributeMaxDynamicSharedMemorySize, HS_SMEM);

    // henc = relu(xcat@p1W^T + p1b) -> fp16 only
    hgemm_small<<<dim3(512 / 128, (NROWS + 63) / 64), 128, HS_SMEM>>>(
        NROWS, 512, 256, xcath, p1h, p1b, nullptr, nullptr, hench, 1);
    // oenc = henc@p2W^T + p2b + xcat
    hgemm_small<<<dim3(256 / 128, (NROWS + 63) / 64), 128, HS_SMEM>>>(
        NROWS, 256, 512, hench, p2h, p2b, xcat, oenc, nullptr, 0);
    ln_kernel<<<NROWS, 256>>>(lng, lnb);

    sconst2_kernel<<<G4 / 32, 256>>>(Whh);

    // qWihb = enc@Wih^T + (b_ih + b_hh)
    hgemm_small<<<dim3(G4 / 128, BQ / 64), 128, HS_SMEM>>>(
        BQ, G4, 256, ench, Wihh, bsum, nullptr, qWihb, nullptr, 0);

    lstm_kernel<<<(BQ * HID + 255) / 256, 256>>>(qWihb, 1);

    for (int s = 1; s < 3; ++s) {
        hgemm_small<<<dim3(G4 / 128, BQ / 64), 128, HS_SMEM>>>(
            BQ, G4, 256, hh, Whhh, sconst, qWihb, gates, nullptr, 0);
        lstm_kernel<<<(BQ * HID + 255) / 256, 256>>>(gates, 0);
    }
    hgemm_small<<<dim3(G4 / 128, BQ / 64), 128, HS_SMEM>>>(
        BQ, G4, 256, hh, Whhh, sconst, qWihb, gates, nullptr, 0);
    lstm_last_kernel<<<BQ, 256>>>(gates, (float*)d_out);
}